// round 8
// baseline (speedup 1.0000x reference)
#include <cuda_runtime.h>
#include <cuda_bf16.h>
#include <cstdint>
#include <math.h>

// Problem constants
#define BB 4
#define SS 2048
#define EE 2048
#define HH 16
#define DD 128
#define DH 64   // DD/2

#define MM (BB * SS)        // 8192
#define NELEM ((size_t)MM * EE)   // 16,777,216
#define WELEM ((size_t)EE * EE)   // 4,194,304

// ---------------------------------------------------------------------------
// Scratch (device globals — no allocation allowed in kernel_launch)
// ---------------------------------------------------------------------------
__device__ float g_q[NELEM];
__device__ float g_k[NELEM];
__device__ float g_v[NELEM];
__device__ float g_attn[NELEM];

__device__ __nv_bfloat16 g_xq_hi[NELEM],  g_xq_lo[NELEM];
__device__ __nv_bfloat16 g_xkv_hi[NELEM], g_xkv_lo[NELEM];
__device__ __nv_bfloat16 g_at_hi[NELEM],  g_at_lo[NELEM];
__device__ __nv_bfloat16 g_wq_hi[WELEM], g_wq_lo[WELEM];
__device__ __nv_bfloat16 g_wk_hi[WELEM], g_wk_lo[WELEM];
__device__ __nv_bfloat16 g_wv_hi[WELEM], g_wv_lo[WELEM];
__device__ __nv_bfloat16 g_wo_hi[WELEM], g_wo_lo[WELEM];

// ---------------------------------------------------------------------------
// helpers
// ---------------------------------------------------------------------------
__device__ __forceinline__ uint32_t smem_u32(const void* p) {
    uint32_t a;
    asm("{ .reg .u64 t; cvta.to.shared.u64 t, %1; cvt.u32.u64 %0, t; }"
        : "=r"(a) : "l"(p));
    return a;
}

__device__ __forceinline__ void ldsm4(uint32_t* r, uint32_t addr) {
    asm volatile("ldmatrix.sync.aligned.m8n8.x4.shared.b16 {%0,%1,%2,%3}, [%4];"
        : "=r"(r[0]), "=r"(r[1]), "=r"(r[2]), "=r"(r[3]) : "r"(addr));
}

__device__ __forceinline__ void mma_bf16(float* d, const uint32_t* a,
                                         const uint32_t* b) {
    asm volatile(
        "mma.sync.aligned.m16n8k16.row.col.f32.bf16.bf16.f32 "
        "{%0,%1,%2,%3}, {%4,%5,%6,%7}, {%8,%9}, {%0,%1,%2,%3};"
        : "+f"(d[0]), "+f"(d[1]), "+f"(d[2]), "+f"(d[3])
        : "r"(a[0]), "r"(a[1]), "r"(a[2]), "r"(a[3]), "r"(b[0]), "r"(b[1]));
}

__device__ __forceinline__ void cp16(uint32_t dst, const void* src) {
    asm volatile("cp.async.ca.shared.global [%0], [%1], 16;"
        :: "r"(dst), "l"((uint64_t)__cvta_generic_to_global(src)));
}
#define CP_COMMIT() asm volatile("cp.async.commit_group;")
#define CP_WAIT(n)  asm volatile("cp.async.wait_group %0;" :: "n"(n))

// ---------------------------------------------------------------------------
// Split fp32 -> (hi, lo) bf16 pair
// ---------------------------------------------------------------------------
__global__ __launch_bounds__(256) void split_kernel(
    const float* __restrict__ src, __nv_bfloat16* __restrict__ hi,
    __nv_bfloat16* __restrict__ lo, size_t n4)
{
    size_t i = (size_t)blockIdx.x * blockDim.x + threadIdx.x;
    if (i >= n4) return;
    float4 v = *(const float4*)(src + i * 4);
    __nv_bfloat16 h[4], l[4];
    const float* f = (const float*)&v;
#pragma unroll
    for (int e = 0; e < 4; e++) {
        h[e] = __float2bfloat16(f[e]);
        l[e] = __float2bfloat16(f[e] - __bfloat162float(h[e]));
    }
    *(uint2*)(hi + i * 4) = *(uint2*)h;
    *(uint2*)(lo + i * 4) = *(uint2*)l;
}

// ---------------------------------------------------------------------------
// Pre-split bf16 tensor-core GEMM v2: C = A @ W^T + bias (3-term split)
// CTA 128x256, BK=32, warp tile 32x128, 2-stage cp.async, 8 warps.
// smem/stage: Ahi,Alo 10240B each + Bhi,Blo 20480B each = 61440; x2 = 122880B
// ---------------------------------------------------------------------------
#define GBM 128
#define GBN 256
#define GBK 32
#define LDS 40
#define A_BYTES (GBM * LDS * 2)    // 10240
#define B_BYTES (GBN * LDS * 2)    // 20480
#define STAGEB (2 * A_BYTES + 2 * B_BYTES)   // 61440
#define SA_HI(s) ((s) * STAGEB)
#define SA_LO(s) ((s) * STAGEB + A_BYTES)
#define SB_HI(s) ((s) * STAGEB + 2 * A_BYTES)
#define SB_LO(s) ((s) * STAGEB + 2 * A_BYTES + B_BYTES)
#define GEMM_SMEM_BYTES (2 * STAGEB)

__global__ __launch_bounds__(256, 1) void gemm_bf16p_kernel(
    const __nv_bfloat16* __restrict__ Ahi, const __nv_bfloat16* __restrict__ Alo,
    const __nv_bfloat16* __restrict__ Bhi, const __nv_bfloat16* __restrict__ Blo,
    const float* __restrict__ bias, float* __restrict__ C,
    int M, int N, int K)
{
    extern __shared__ __align__(16) char dsmem[];
    const uint32_t sb = smem_u32(dsmem);

    const int tid  = threadIdx.x;
    const int lane = tid & 31;
    const int wid  = tid >> 5;
    const int wm   = wid & 3;      // 0..3 -> 32-row band
    const int wn   = wid >> 2;     // 0..1 -> 128-col band
    const size_t m0 = (size_t)blockIdx.y * GBM;
    const size_t n0 = (size_t)blockIdx.x * GBN;

    float acc[2][16][4];
#pragma unroll
    for (int i = 0; i < 2; i++)
#pragma unroll
        for (int j = 0; j < 16; j++)
#pragma unroll
            for (int e = 0; e < 4; e++) acc[i][j][e] = 0.f;

    // cp.async mapping:
    //   A (512 segs of 16B per matrix): thread t -> row t>>1, cols (t&1)*2+{0,1}
    //   B (1024 segs per matrix): thread t -> row t, cols 0..3
    const int ra  = tid >> 1;
    const int csA = (tid & 1) * 2;

    // ldmatrix lane addressing
    const int a_row = wm * 32 + (lane & 15);
    const int a_col = (lane >> 4) << 3;
    const int b_row = wn * 128 + ((lane >> 4) << 3) + (lane & 7);
    const int b_col = ((lane >> 3) & 1) << 3;

    const int nChunks = K / GBK;   // 64

#define PREFETCH(c, s) do {                                                      \
    size_t ca = (size_t)(c) * GBK;                                               \
    uint32_t dA = (uint32_t)(ra * 80 + csA * 16);                                \
    const __nv_bfloat16* pAh = Ahi + (m0 + ra) * K + ca + csA * 8;               \
    const __nv_bfloat16* pAl = Alo + (m0 + ra) * K + ca + csA * 8;               \
    cp16(sb + SA_HI(s) + dA,      pAh);                                          \
    cp16(sb + SA_HI(s) + dA + 16, pAh + 8);                                      \
    cp16(sb + SA_LO(s) + dA,      pAl);                                          \
    cp16(sb + SA_LO(s) + dA + 16, pAl + 8);                                      \
    uint32_t dB = (uint32_t)(tid * 80);                                          \
    const __nv_bfloat16* pBh = Bhi + (n0 + tid) * K + ca;                        \
    const __nv_bfloat16* pBl = Blo + (n0 + tid) * K + ca;                        \
    cp16(sb + SB_HI(s) + dB,      pBh);                                          \
    cp16(sb + SB_HI(s) + dB + 16, pBh + 8);                                      \
    cp16(sb + SB_HI(s) + dB + 32, pBh + 16);                                     \
    cp16(sb + SB_HI(s) + dB + 48, pBh + 24);                                     \
    cp16(sb + SB_LO(s) + dB,      pBl);                                          \
    cp16(sb + SB_LO(s) + dB + 16, pBl + 8);                                      \
    cp16(sb + SB_LO(s) + dB + 32, pBl + 16);                                     \
    cp16(sb + SB_LO(s) + dB + 48, pBl + 24);                                     \
} while (0)

    PREFETCH(0, 0);
    CP_COMMIT();

    for (int c = 0; c < nChunks; c++) {
        const int s = c & 1;
        if (c + 1 < nChunks) {
            PREFETCH(c + 1, s ^ 1);
            CP_COMMIT();
            CP_WAIT(1);
        } else {
            CP_WAIT(0);
        }
        __syncthreads();

        const uint32_t uAhi = sb + SA_HI(s);
        const uint32_t uAlo = sb + SA_LO(s);
        const uint32_t uBhi = sb + SB_HI(s);
        const uint32_t uBlo = sb + SB_LO(s);

#pragma unroll
        for (int ks = 0; ks < 2; ks++) {
            const int kk = ks * 16;
            uint32_t ahi[2][4], alo[2][4];
#pragma unroll
            for (int mi = 0; mi < 2; mi++) {
                uint32_t aoff = (uint32_t)(((a_row + mi * 16) * LDS + kk + a_col) * 2);
                ldsm4(ahi[mi], uAhi + aoff);
                ldsm4(alo[mi], uAlo + aoff);
            }
#pragma unroll
            for (int nb = 0; nb < 8; nb++) {
                uint32_t boff = (uint32_t)(((b_row + nb * 16) * LDS + kk + b_col) * 2);
                uint32_t bh[4], bl[4];
                ldsm4(bh, uBhi + boff);
                ldsm4(bl, uBlo + boff);
#pragma unroll
                for (int mi = 0; mi < 2; mi++) {
                    mma_bf16(acc[mi][nb * 2 + 0], ahi[mi], bh + 0);
                    mma_bf16(acc[mi][nb * 2 + 1], ahi[mi], bh + 2);
                    mma_bf16(acc[mi][nb * 2 + 0], ahi[mi], bl + 0);
                    mma_bf16(acc[mi][nb * 2 + 1], ahi[mi], bl + 2);
                    mma_bf16(acc[mi][nb * 2 + 0], alo[mi], bh + 0);
                    mma_bf16(acc[mi][nb * 2 + 1], alo[mi], bh + 2);
                }
            }
        }
        __syncthreads();
    }

    // epilogue: warp writes 32 rows x 128 cols
    const int er = lane >> 2;
    const int ec = (lane & 3) * 2;
#pragma unroll
    for (int mi = 0; mi < 2; mi++) {
#pragma unroll
        for (int nbb = 0; nbb < 16; nbb++) {
            size_t row0 = m0 + wm * 32 + mi * 16 + er;
            size_t col  = n0 + wn * 128 + nbb * 8 + ec;
            float b0 = __ldg(bias + col);
            float b1 = __ldg(bias + col + 1);
            float2 o0 = make_float2(acc[mi][nbb][0] + b0, acc[mi][nbb][1] + b1);
            float2 o1 = make_float2(acc[mi][nbb][2] + b0, acc[mi][nbb][3] + b1);
            *(float2*)(C + row0 * (size_t)N + col)       = o0;
            *(float2*)(C + (row0 + 8) * (size_t)N + col) = o1;
        }
    }
}

// ---------------------------------------------------------------------------
// RoPE, in-place on [B,S,H,D]. angles: [2][S][DH] (0=sin, 1=cos).
// ---------------------------------------------------------------------------
__global__ __launch_bounds__(256) void rope_kernel(
    float* __restrict__ x, const float* __restrict__ angles,
    const int* __restrict__ flag, int always)
{
    if (!always && *flag == 0) return;
    size_t i = (size_t)blockIdx.x * blockDim.x + threadIdx.x;
    const size_t total = (size_t)BB * SS * HH * DH;
    if (i >= total) return;
    int half = (int)(i % DH);
    int h    = (int)((i / DH) % HH);
    int s    = (int)((i / ((size_t)DH * HH)) % SS);
    int b    = (int)(i / ((size_t)DH * HH * SS));

    float sn = angles[(size_t)s * DH + half];
    float cs = angles[(size_t)SS * DH + (size_t)s * DH + half];

    size_t base = (((size_t)b * SS + s) * HH + h) * (size_t)DD;
    float x1 = x[base + half];
    float x2 = x[base + DH + half];
    x[base + half]      = x1 * cs - x2 * sn;
    x[base + DH + half] = x1 * sn + x2 * cs;
}

// ---------------------------------------------------------------------------
// Flash attention (fp32). One CTA = (b,h, 64 q-rows). 256 threads.
// ---------------------------------------------------------------------------
#define AQ 64
#define AK 64
#define QTP 68

__global__ __launch_bounds__(256) void attn_kernel(
    const float* __restrict__ q, const float* __restrict__ k,
    const float* __restrict__ v, const int* __restrict__ amask,
    const int* __restrict__ causal_ptr, float* __restrict__ outp)
{
    extern __shared__ float sm[];
    float* Qt = sm;
    float* Kt = sm + 8704;
    float* Vs = sm + 17408;
    float* Ps = sm + 25600;
    int*   km = (int*)(sm + 29696);

    const int tid = threadIdx.x;
    const int ty = tid >> 4;
    const int tx = tid & 15;
    const int bh = blockIdx.x;
    const int b  = bh >> 4;
    const int h  = bh & 15;
    const int q0 = blockIdx.y * AQ;
    const int causal = *causal_ptr;

    const size_t rowStride = (size_t)HH * DD;
    const float* qb = q + ((size_t)b * SS + q0) * rowStride + (size_t)h * DD;

    for (int i = tid; i < AQ * 32; i += 256) {
        int r  = i >> 5;
        int c4 = (i & 31) * 4;
        float4 vq = *(const float4*)(qb + (size_t)r * rowStride + c4);
        Qt[(c4 + 0) * QTP + r] = vq.x;
        Qt[(c4 + 1) * QTP + r] = vq.y;
        Qt[(c4 + 2) * QTP + r] = vq.z;
        Qt[(c4 + 3) * QTP + r] = vq.w;
    }

    float accv[4][8];
#pragma unroll
    for (int i = 0; i < 4; i++)
#pragma unroll
        for (int j = 0; j < 8; j++) accv[i][j] = 0.f;
    float mi[4], li[4];
#pragma unroll
    for (int i = 0; i < 4; i++) { mi[i] = -1e30f; li[i] = 0.f; }

    const float scale = 0.0883883476483184f;

    for (int kt = 0; kt < SS / AK; kt++) {
        __syncthreads();

        const float* kb = k + ((size_t)b * SS + kt * AK) * rowStride + (size_t)h * DD;
        const float* vb = v + ((size_t)b * SS + kt * AK) * rowStride + (size_t)h * DD;
        for (int i = tid; i < AK * 32; i += 256) {
            int r  = i >> 5;
            int c4 = (i & 31) * 4;
            float4 kv = *(const float4*)(kb + (size_t)r * rowStride + c4);
            Kt[(c4 + 0) * QTP + r] = kv.x;
            Kt[(c4 + 1) * QTP + r] = kv.y;
            Kt[(c4 + 2) * QTP + r] = kv.z;
            Kt[(c4 + 3) * QTP + r] = kv.w;
            float4 vv = *(const float4*)(vb + (size_t)r * rowStride + c4);
            *(float4*)&Vs[r * DD + c4] = vv;
        }
        if (tid < AK) km[tid] = amask[(size_t)b * SS + kt * AK + tid];
        __syncthreads();

        float sf[4][4];
#pragma unroll
        for (int i = 0; i < 4; i++)
#pragma unroll
            for (int j = 0; j < 4; j++) sf[i][j] = 0.f;

#pragma unroll 8
        for (int d = 0; d < DD; d++) {
            float4 qv = *(const float4*)&Qt[d * QTP + ty * 4];
            float4 kv = *(const float4*)&Kt[d * QTP + tx * 4];
            sf[0][0] += qv.x * kv.x; sf[0][1] += qv.x * kv.y;
            sf[0][2] += qv.x * kv.z; sf[0][3] += qv.x * kv.w;
            sf[1][0] += qv.y * kv.x; sf[1][1] += qv.y * kv.y;
            sf[1][2] += qv.y * kv.z; sf[1][3] += qv.y * kv.w;
            sf[2][0] += qv.z * kv.x; sf[2][1] += qv.z * kv.y;
            sf[2][2] += qv.z * kv.z; sf[2][3] += qv.z * kv.w;
            sf[3][0] += qv.w * kv.x; sf[3][1] += qv.w * kv.y;
            sf[3][2] += qv.w * kv.z; sf[3][3] += qv.w * kv.w;
        }

#pragma unroll
        for (int i = 0; i < 4; i++) {
            int qg = q0 + ty * 4 + i;
#pragma unroll
            for (int j = 0; j < 4; j++) {
                int kg = kt * AK + tx * 4 + j;
                bool ok = (km[tx * 4 + j] != 0) && (!causal || kg <= qg);
                sf[i][j] = ok ? sf[i][j] * scale : -1e30f;
            }
        }

#pragma unroll
        for (int i = 0; i < 4; i++) {
            float tmax = fmaxf(fmaxf(sf[i][0], sf[i][1]), fmaxf(sf[i][2], sf[i][3]));
#pragma unroll
            for (int o = 8; o > 0; o >>= 1)
                tmax = fmaxf(tmax, __shfl_xor_sync(0xffffffffu, tmax, o));
            float nm = fmaxf(mi[i], tmax);

            float p[4], rs = 0.f;
#pragma unroll
            for (int j = 0; j < 4; j++) {
                p[j] = (sf[i][j] <= -1e29f) ? 0.f : __expf(sf[i][j] - nm);
                rs += p[j];
            }
#pragma unroll
            for (int o = 8; o > 0; o >>= 1)
                rs += __shfl_xor_sync(0xffffffffu, rs, o);

            float alpha = __expf(mi[i] - nm);
            li[i] = li[i] * alpha + rs;
            mi[i] = nm;
#pragma unroll
            for (int jj = 0; jj < 8; jj++) accv[i][jj] *= alpha;

            *(float4*)&Ps[(ty * 4 + i) * AK + tx * 4] = make_float4(p[0], p[1], p[2], p[3]);
        }
        __syncthreads();

#pragma unroll 4
        for (int c = 0; c < AK; c++) {
            float4 v0 = *(const float4*)&Vs[c * DD + tx * 8];
            float4 v1 = *(const float4*)&Vs[c * DD + tx * 8 + 4];
#pragma unroll
            for (int i = 0; i < 4; i++) {
                float pp = Ps[(ty * 4 + i) * AK + c];
                accv[i][0] += pp * v0.x; accv[i][1] += pp * v0.y;
                accv[i][2] += pp * v0.z; accv[i][3] += pp * v0.w;
                accv[i][4] += pp * v1.x; accv[i][5] += pp * v1.y;
                accv[i][6] += pp * v1.z; accv[i][7] += pp * v1.w;
            }
        }
    }

    float* ob = outp + ((size_t)b * SS + q0) * rowStride + (size_t)h * DD;
#pragma unroll
    for (int i = 0; i < 4; i++) {
        float inv = (li[i] > 0.f) ? 1.f / li[i] : 0.f;
        int r = ty * 4 + i;
        float4 o0 = make_float4(accv[i][0] * inv, accv[i][1] * inv,
                                accv[i][2] * inv, accv[i][3] * inv);
        float4 o1 = make_float4(accv[i][4] * inv, accv[i][5] * inv,
                                accv[i][6] * inv, accv[i][7] * inv);
        *(float4*)(ob + (size_t)r * rowStride + tx * 8)     = o0;
        *(float4*)(ob + (size_t)r * rowStride + tx * 8 + 4) = o1;
    }
}

// ---------------------------------------------------------------------------
// Launch  (order matters: ncu -s 5 -c 1 profiles launch #6 = GEMM-Q)
// ---------------------------------------------------------------------------
extern "C" void kernel_launch(void* const* d_in, const int* in_sizes, int n_in,
                              void* d_out, int out_size)
{
    const float* x_q    = (const float*)d_in[0];
    const float* x_kv   = (const float*)d_in[1];
    const float* Wq     = (const float*)d_in[2];
    const float* bq     = (const float*)d_in[3];
    const float* Wk     = (const float*)d_in[4];
    const float* bk     = (const float*)d_in[5];
    const float* Wv     = (const float*)d_in[6];
    const float* bv     = (const float*)d_in[7];
    const float* Wo     = (const float*)d_in[8];
    const float* bo     = (const float*)d_in[9];
    const float* angles = (const float*)d_in[10];
    const int*   amask  = (const int*)d_in[11];
    const int*   causal = (const int*)d_in[12];
    const int*   k_rope = (const int*)d_in[13];
    float* out = (float*)d_out;

    float *q, *k, *v, *attn;
    cudaGetSymbolAddress((void**)&q,    g_q);
    cudaGetSymbolAddress((void**)&k,    g_k);
    cudaGetSymbolAddress((void**)&v,    g_v);
    cudaGetSymbolAddress((void**)&attn, g_attn);

    __nv_bfloat16 *xq_hi, *xq_lo, *xkv_hi, *xkv_lo, *at_hi, *at_lo;
    __nv_bfloat16 *wq_hi, *wq_lo, *wk_hi, *wk_lo, *wv_hi, *wv_lo, *wo_hi, *wo_lo;
    cudaGetSymbolAddress((void**)&xq_hi,  g_xq_hi);
    cudaGetSymbolAddress((void**)&xq_lo,  g_xq_lo);
    cudaGetSymbolAddress((void**)&xkv_hi, g_xkv_hi);
    cudaGetSymbolAddress((void**)&xkv_lo, g_xkv_lo);
    cudaGetSymbolAddress((void**)&at_hi,  g_at_hi);
    cudaGetSymbolAddress((void**)&at_lo,  g_at_lo);
    cudaGetSymbolAddress((void**)&wq_hi,  g_wq_hi);
    cudaGetSymbolAddress((void**)&wq_lo,  g_wq_lo);
    cudaGetSymbolAddress((void**)&wk_hi,  g_wk_hi);
    cudaGetSymbolAddress((void**)&wk_lo,  g_wk_lo);
    cudaGetSymbolAddress((void**)&wv_hi,  g_wv_hi);
    cudaGetSymbolAddress((void**)&wv_lo,  g_wv_lo);
    cudaGetSymbolAddress((void**)&wo_hi,  g_wo_hi);
    cudaGetSymbolAddress((void**)&wo_lo,  g_wo_lo);

    const int M = MM;        // 8192
    const int N = EE;        // 2048
    const int K = EE;        // 2048

    const int xBlocks = (int)(NELEM / 4 / 256);
    const int wBlocks = (int)(WELEM / 4 / 256);

    cudaFuncSetAttribute(gemm_bf16p_kernel,
                         cudaFuncAttributeMaxDynamicSharedMemorySize, GEMM_SMEM_BYTES);
    dim3 gGrid(N / GBN, M / GBM);   // (8, 64)

    // launches 1-5: splits needed for the first GEMM
    split_kernel<<<xBlocks, 256>>>(x_q,  xq_hi,  xq_lo,  NELEM / 4);
    split_kernel<<<xBlocks, 256>>>(x_kv, xkv_hi, xkv_lo, NELEM / 4);
    split_kernel<<<wBlocks, 256>>>(Wq, wq_hi, wq_lo, WELEM / 4);
    split_kernel<<<wBlocks, 256>>>(Wk, wk_hi, wk_lo, WELEM / 4);
    split_kernel<<<wBlocks, 256>>>(Wv, wv_hi, wv_lo, WELEM / 4);
    // launch 6: profiled by ncu (-s 5 -c 1)
    gemm_bf16p_kernel<<<gGrid, 256, GEMM_SMEM_BYTES>>>(xq_hi,  xq_lo,  wq_hi, wq_lo, bq, q, M, N, K);
    gemm_bf16p_kernel<<<gGrid, 256, GEMM_SMEM_BYTES>>>(xkv_hi, xkv_lo, wk_hi, wk_lo, bk, k, M, N, K);
    gemm_bf16p_kernel<<<gGrid, 256, GEMM_SMEM_BYTES>>>(xkv_hi, xkv_lo, wv_hi, wv_lo, bv, v, M, N, K);
    split_kernel<<<wBlocks, 256>>>(Wo, wo_hi, wo_lo, WELEM / 4);

    size_t ropeTotal = (size_t)BB * SS * HH * DH;
    int ropeBlocks = (int)((ropeTotal + 255) / 256);
    rope_kernel<<<ropeBlocks, 256>>>(q, angles, k_rope, 1);
    rope_kernel<<<ropeBlocks, 256>>>(k, angles, k_rope, 0);

    const int smemBytes = 119040;
    cudaFuncSetAttribute(attn_kernel, cudaFuncAttributeMaxDynamicSharedMemorySize, smemBytes);
    dim3 aGrid(BB * HH, SS / AQ);   // (64, 32)
    attn_kernel<<<aGrid, 256, smemBytes>>>(q, k, v, amask, causal, attn);

    split_kernel<<<xBlocks, 256>>>(attn, at_hi, at_lo, NELEM / 4);
    gemm_bf16p_kernel<<<gGrid, 256, GEMM_SMEM_BYTES>>>(at_hi, at_lo, wo_hi, wo_lo, bo, out, M, N, K);
}

// round 9
// speedup vs baseline: 1.9900x; 1.9900x over previous
#include <cuda_runtime.h>
#include <cuda_bf16.h>
#include <cstdint>
#include <math.h>

// Problem constants
#define BB 4
#define SS 2048
#define EE 2048
#define HH 16
#define DD 128
#define DH 64   // DD/2

#define MM (BB * SS)              // 8192
#define NELEM ((size_t)MM * EE)   // 16,777,216
#define WELEM ((size_t)EE * EE)   // 4,194,304

// ---------------------------------------------------------------------------
// Scratch (device globals — no allocation allowed in kernel_launch)
// ---------------------------------------------------------------------------
__device__ float g_q[NELEM];
__device__ float g_k[NELEM];
__device__ float g_v[NELEM];

__device__ __nv_bfloat16 g_xq_hi[NELEM],  g_xq_lo[NELEM];   // later reused: q hi/lo
__device__ __nv_bfloat16 g_xkv_hi[NELEM], g_xkv_lo[NELEM];  // later reused: k hi/lo
__device__ __nv_bfloat16 g_v_hi[NELEM],   g_v_lo[NELEM];    // v hi/lo
__device__ __nv_bfloat16 g_at_hi[NELEM],  g_at_lo[NELEM];   // attn output hi/lo
__device__ __nv_bfloat16 g_wq_hi[WELEM], g_wq_lo[WELEM];
__device__ __nv_bfloat16 g_wk_hi[WELEM], g_wk_lo[WELEM];
__device__ __nv_bfloat16 g_wv_hi[WELEM], g_wv_lo[WELEM];
__device__ __nv_bfloat16 g_wo_hi[WELEM], g_wo_lo[WELEM];

// ---------------------------------------------------------------------------
// helpers
// ---------------------------------------------------------------------------
__device__ __forceinline__ uint32_t smem_u32(const void* p) {
    uint32_t a;
    asm("{ .reg .u64 t; cvta.to.shared.u64 t, %1; cvt.u32.u64 %0, t; }"
        : "=r"(a) : "l"(p));
    return a;
}

__device__ __forceinline__ void ldsm4(uint32_t* r, uint32_t addr) {
    asm volatile("ldmatrix.sync.aligned.m8n8.x4.shared.b16 {%0,%1,%2,%3}, [%4];"
        : "=r"(r[0]), "=r"(r[1]), "=r"(r[2]), "=r"(r[3]) : "r"(addr));
}

__device__ __forceinline__ void ldsm4t(uint32_t* r, uint32_t addr) {
    asm volatile("ldmatrix.sync.aligned.m8n8.x4.trans.shared.b16 {%0,%1,%2,%3}, [%4];"
        : "=r"(r[0]), "=r"(r[1]), "=r"(r[2]), "=r"(r[3]) : "r"(addr));
}

__device__ __forceinline__ void mma_bf16(float* d, const uint32_t* a,
                                         const uint32_t* b) {
    asm volatile(
        "mma.sync.aligned.m16n8k16.row.col.f32.bf16.bf16.f32 "
        "{%0,%1,%2,%3}, {%4,%5,%6,%7}, {%8,%9}, {%0,%1,%2,%3};"
        : "+f"(d[0]), "+f"(d[1]), "+f"(d[2]), "+f"(d[3])
        : "r"(a[0]), "r"(a[1]), "r"(a[2]), "r"(a[3]), "r"(b[0]), "r"(b[1]));
}

__device__ __forceinline__ void cp16(uint32_t dst, const void* src) {
    asm volatile("cp.async.ca.shared.global [%0], [%1], 16;"
        :: "r"(dst), "l"((uint64_t)__cvta_generic_to_global(src)));
}
#define CP_COMMIT() asm volatile("cp.async.commit_group;")
#define CP_WAIT(n)  asm volatile("cp.async.wait_group %0;" :: "n"(n))

// ---------------------------------------------------------------------------
// Split fp32 -> (hi, lo) bf16 pair
// ---------------------------------------------------------------------------
__global__ __launch_bounds__(256) void split_kernel(
    const float* __restrict__ src, __nv_bfloat16* __restrict__ hi,
    __nv_bfloat16* __restrict__ lo, size_t n4)
{
    size_t i = (size_t)blockIdx.x * blockDim.x + threadIdx.x;
    if (i >= n4) return;
    float4 v = *(const float4*)(src + i * 4);
    __nv_bfloat16 h[4], l[4];
    const float* f = (const float*)&v;
#pragma unroll
    for (int e = 0; e < 4; e++) {
        h[e] = __float2bfloat16(f[e]);
        l[e] = __float2bfloat16(f[e] - __bfloat162float(h[e]));
    }
    *(uint2*)(hi + i * 4) = *(uint2*)h;
    *(uint2*)(lo + i * 4) = *(uint2*)l;
}

// ---------------------------------------------------------------------------
// Pre-split bf16 tensor-core GEMM (R7 config, VALIDATED): C = A @ W^T + bias
// CTA 128x128, BK=32, 2-stage cp.async, 8 warps, 2 CTAs/SM.
// ---------------------------------------------------------------------------
#define GBM 128
#define GBN 128
#define GBK 32
#define LDS 40
#define BUFB (GBM * LDS * 2)       // 10240 bytes per buffer
#define GEMM_SMEM_BYTES (BUFB * 8)

__global__ __launch_bounds__(256) void gemm_bf16p_kernel(
    const __nv_bfloat16* __restrict__ Ahi, const __nv_bfloat16* __restrict__ Alo,
    const __nv_bfloat16* __restrict__ Bhi, const __nv_bfloat16* __restrict__ Blo,
    const float* __restrict__ bias, float* __restrict__ C,
    int M, int N, int K)
{
    extern __shared__ __align__(16) char dsmem[];
    const uint32_t sb = smem_u32(dsmem);

    const int tid  = threadIdx.x;
    const int lane = tid & 31;
    const int wid  = tid >> 5;
    const int wm   = wid & 3;
    const int wn   = wid >> 2;
    const size_t m0 = (size_t)blockIdx.y * GBM;
    const size_t n0 = (size_t)blockIdx.x * GBN;

    float acc[2][8][4];
#pragma unroll
    for (int i = 0; i < 2; i++)
#pragma unroll
        for (int j = 0; j < 8; j++)
#pragma unroll
            for (int e = 0; e < 4; e++) acc[i][j][e] = 0.f;

    const int seg0 = tid * 2;
    const int r0 = seg0 >> 2,        cs0 = seg0 & 3;
    const int r1 = (seg0 + 1) >> 2,  cs1 = (seg0 + 1) & 3;

    const int a_row = wm * 32 + (lane & 15);
    const int a_col = (lane >> 4) << 3;
    const int b_row = wn * 64 + ((lane >> 4) << 3) + (lane & 7);
    const int b_col = ((lane >> 3) & 1) << 3;

    const int nChunks = K / GBK;

#define PREFETCH(c, s) do {                                                     \
    size_t ca = (size_t)(c) * GBK;                                              \
    uint32_t d0 = (uint32_t)(r0 * 80 + cs0 * 16);                               \
    uint32_t d1 = (uint32_t)(r1 * 80 + cs1 * 16);                               \
    cp16(sb + (0 + (s)) * BUFB + d0, Ahi + (m0 + r0) * K + ca + cs0 * 8);       \
    cp16(sb + (0 + (s)) * BUFB + d1, Ahi + (m0 + r1) * K + ca + cs1 * 8);       \
    cp16(sb + (2 + (s)) * BUFB + d0, Alo + (m0 + r0) * K + ca + cs0 * 8);       \
    cp16(sb + (2 + (s)) * BUFB + d1, Alo + (m0 + r1) * K + ca + cs1 * 8);       \
    cp16(sb + (4 + (s)) * BUFB + d0, Bhi + (n0 + r0) * K + ca + cs0 * 8);       \
    cp16(sb + (4 + (s)) * BUFB + d1, Bhi + (n0 + r1) * K + ca + cs1 * 8);       \
    cp16(sb + (6 + (s)) * BUFB + d0, Blo + (n0 + r0) * K + ca + cs0 * 8);       \
    cp16(sb + (6 + (s)) * BUFB + d1, Blo + (n0 + r1) * K + ca + cs1 * 8);       \
} while (0)

    PREFETCH(0, 0);
    CP_COMMIT();

    for (int c = 0; c < nChunks; c++) {
        const int s = c & 1;
        if (c + 1 < nChunks) {
            PREFETCH(c + 1, s ^ 1);
            CP_COMMIT();
            CP_WAIT(1);
        } else {
            CP_WAIT(0);
        }
        __syncthreads();

        const uint32_t uAhi = sb + (0 + s) * BUFB;
        const uint32_t uAlo = sb + (2 + s) * BUFB;
        const uint32_t uBhi = sb + (4 + s) * BUFB;
        const uint32_t uBlo = sb + (6 + s) * BUFB;

#pragma unroll
        for (int ks = 0; ks < 2; ks++) {
            const int kk = ks * 16;
            uint32_t ahi[2][4], alo[2][4];
#pragma unroll
            for (int mi = 0; mi < 2; mi++) {
                uint32_t aoff = (uint32_t)(((a_row + mi * 16) * LDS + kk + a_col) * 2);
                ldsm4(ahi[mi], uAhi + aoff);
                ldsm4(alo[mi], uAlo + aoff);
            }
#pragma unroll
            for (int nb = 0; nb < 4; nb++) {
                uint32_t boff = (uint32_t)(((b_row + nb * 16) * LDS + kk + b_col) * 2);
                uint32_t bh[4], bl[4];
                ldsm4(bh, uBhi + boff);
                ldsm4(bl, uBlo + boff);
#pragma unroll
                for (int mi = 0; mi < 2; mi++) {
                    mma_bf16(acc[mi][nb * 2 + 0], ahi[mi], bh + 0);
                    mma_bf16(acc[mi][nb * 2 + 1], ahi[mi], bh + 2);
                    mma_bf16(acc[mi][nb * 2 + 0], ahi[mi], bl + 0);
                    mma_bf16(acc[mi][nb * 2 + 1], ahi[mi], bl + 2);
                    mma_bf16(acc[mi][nb * 2 + 0], alo[mi], bh + 0);
                    mma_bf16(acc[mi][nb * 2 + 1], alo[mi], bh + 2);
                }
            }
        }
        __syncthreads();
    }

    const int er = lane >> 2;
    const int ec = (lane & 3) * 2;
#pragma unroll
    for (int mi = 0; mi < 2; mi++) {
#pragma unroll
        for (int nbb = 0; nbb < 8; nbb++) {
            size_t row0 = m0 + wm * 32 + mi * 16 + er;
            size_t col  = n0 + wn * 64 + nbb * 8 + ec;
            float b0 = __ldg(bias + col);
            float b1 = __ldg(bias + col + 1);
            float2 o0 = make_float2(acc[mi][nbb][0] + b0, acc[mi][nbb][1] + b1);
            float2 o1 = make_float2(acc[mi][nbb][2] + b0, acc[mi][nbb][3] + b1);
            *(float2*)(C + row0 * (size_t)N + col)       = o0;
            *(float2*)(C + (row0 + 8) * (size_t)N + col) = o1;
        }
    }
}

// ---------------------------------------------------------------------------
// RoPE, in-place on [B,S,H,D]. angles: [2][S][DH] (0=sin, 1=cos).
// ---------------------------------------------------------------------------
__global__ __launch_bounds__(256) void rope_kernel(
    float* __restrict__ x, const float* __restrict__ angles,
    const int* __restrict__ flag, int always)
{
    if (!always && *flag == 0) return;
    size_t i = (size_t)blockIdx.x * blockDim.x + threadIdx.x;
    const size_t total = (size_t)BB * SS * HH * DH;
    if (i >= total) return;
    int half = (int)(i % DH);
    int h    = (int)((i / DH) % HH);
    int s    = (int)((i / ((size_t)DH * HH)) % SS);
    int b    = (int)(i / ((size_t)DH * HH * SS));

    float sn = angles[(size_t)s * DH + half];
    float cs = angles[(size_t)SS * DH + (size_t)s * DH + half];

    size_t base = (((size_t)b * SS + s) * HH + h) * (size_t)DD;
    float x1 = x[base + half];
    float x2 = x[base + DH + half];
    x[base + half]      = x1 * cs - x2 * sn;
    x[base + DH + half] = x1 * sn + x2 * cs;
}

// ---------------------------------------------------------------------------
// Flash attention with 3-term split-bf16 mma.sync.
// CTA = (b,h) x 64 q rows, 256 threads / 8 warps (wq 0-3 q-bands, wk 0-1).
// S staged to smem fp32 -> validated online-softmax -> P hi/lo -> PV mma.
// ---------------------------------------------------------------------------
#define ATQ 64
#define ATK 64
#define LQK 136   // element stride for Q/K/V tiles (272B rows)
#define LP  72    // element stride for P tiles (144B rows)
#define LSS 68    // float stride for S scratch

#define AOFF_Q   0u          // Qhi @0, Qlo @17408
#define AOFF_K   34816u      // [s]{Khi,Klo}: s*34816 + {0,17408}
#define AOFF_V   104448u     // [s]{Vhi,Vlo}
#define AOFF_S   174080u     // 64*68*4
#define AOFF_P   191488u     // Phi @0, Plo @9216
#define AOFF_AL  209920u     // alpha[64] f32
#define AOFF_LI  210176u     // linv[64] f32
#define AOFF_KM  210432u     // mask[2][64] i32
#define ATTN_SMEM_BYTES 210944

__global__ __launch_bounds__(256, 1) void attn_mma_kernel(
    const __nv_bfloat16* __restrict__ qhi, const __nv_bfloat16* __restrict__ qlo,
    const __nv_bfloat16* __restrict__ khi, const __nv_bfloat16* __restrict__ klo,
    const __nv_bfloat16* __restrict__ vhi, const __nv_bfloat16* __restrict__ vlo,
    const int* __restrict__ amask, const int* __restrict__ causal_ptr,
    __nv_bfloat16* __restrict__ ohi, __nv_bfloat16* __restrict__ olo)
{
    extern __shared__ __align__(16) char dsmem[];
    const uint32_t sb = smem_u32(dsmem);
    float* Ss    = (float*)(dsmem + AOFF_S);
    float* sAl   = (float*)(dsmem + AOFF_AL);
    float* sLi   = (float*)(dsmem + AOFF_LI);

    const int tid  = threadIdx.x;
    const int lane = tid & 31;
    const int wid  = tid >> 5;
    const int wq   = wid & 3;
    const int wk   = wid >> 2;
    const int b  = blockIdx.x >> 4;
    const int h  = blockIdx.x & 15;
    const int q0 = blockIdx.y * ATQ;
    const int causal = *causal_ptr;

    // softmax mapping (validated R1 layout)
    const int ty = tid >> 4;
    const int tx = tid & 15;
    const float scale = 0.0883883476483184f;   // 1/sqrt(128)

    // fragment addressing (validated GEMM patterns)
    const int a_row = wq * 16 + (lane & 15);
    const int a_col = (lane >> 4) << 3;
    const int b_row = wk * 32 + ((lane >> 4) << 3) + (lane & 7);
    const int b_col = ((lane >> 3) & 1) << 3;
    // V trans-ldmatrix lane addressing
    const int vt_row = lane & 15;
    const int vt_seg = (lane >> 4) << 3;

    // prologue: load Q hi/lo (64 x 128)
    const size_t gq = ((size_t)b * SS + q0) * 2048 + (size_t)h * 128;
#pragma unroll
    for (int it = 0; it < 4; it++) {
        int i = tid + it * 256;
        int r = i >> 4, sg = i & 15;
        uint32_t off = (uint32_t)(r * 272 + sg * 16);
        cp16(sb + AOFF_Q + off,         qhi + gq + (size_t)r * 2048 + sg * 8);
        cp16(sb + AOFF_Q + 17408 + off, qlo + gq + (size_t)r * 2048 + sg * 8);
    }

#define PREFETCH_KV(t, s) do {                                                   \
    size_t gk = ((size_t)b * SS + (size_t)(t) * ATK) * 2048 + (size_t)h * 128;   \
    for (int it = 0; it < 4; it++) {                                             \
        int i = tid + it * 256;                                                  \
        int r = i >> 4, sg = i & 15;                                             \
        uint32_t off = (uint32_t)(r * 272 + sg * 16);                            \
        size_t go = (size_t)r * 2048 + sg * 8;                                   \
        cp16(sb + AOFF_K + (s) * 34816u + off,          khi + gk + go);          \
        cp16(sb + AOFF_K + (s) * 34816u + 17408 + off,  klo + gk + go);          \
        cp16(sb + AOFF_V + (s) * 34816u + off,          vhi + gk + go);          \
        cp16(sb + AOFF_V + (s) * 34816u + 17408 + off,  vlo + gk + go);          \
    }                                                                            \
    if (tid < 16)                                                                \
        cp16(sb + AOFF_KM + (s) * 256u + tid * 16,                               \
             amask + (size_t)b * SS + (size_t)(t) * ATK + tid * 4);              \
} while (0)

    float oacc[8][4];
#pragma unroll
    for (int j = 0; j < 8; j++)
#pragma unroll
        for (int e = 0; e < 4; e++) oacc[j][e] = 0.f;
    float mi[4], li[4];
#pragma unroll
    for (int i = 0; i < 4; i++) { mi[i] = -1e30f; li[i] = 0.f; }

    PREFETCH_KV(0, 0);
    CP_COMMIT();

    const int nTiles = SS / ATK;   // 32
    for (int t = 0; t < nTiles; t++) {
        const int s = t & 1;
        if (t + 1 < nTiles) {
            PREFETCH_KV(t + 1, s ^ 1);
            CP_COMMIT();
            CP_WAIT(1);
        } else {
            CP_WAIT(0);
        }
        __syncthreads();   // K/V/mask[s] visible; prev tile fully done with smem

        // ---- S = Q K^T (3-term) ----
        const uint32_t uQhi = sb + AOFF_Q;
        const uint32_t uQlo = sb + AOFF_Q + 17408;
        const uint32_t uKhi = sb + AOFF_K + s * 34816u;
        const uint32_t uKlo = uKhi + 17408;

        float sacc[4][4];
#pragma unroll
        for (int j = 0; j < 4; j++)
#pragma unroll
            for (int e = 0; e < 4; e++) sacc[j][e] = 0.f;

#pragma unroll
        for (int ks = 0; ks < 8; ks++) {
            const int kk = ks * 16;
            uint32_t qh[4], ql[4];
            uint32_t aoff = (uint32_t)((a_row * LQK + kk + a_col) * 2);
            ldsm4(qh, uQhi + aoff);
            ldsm4(ql, uQlo + aoff);
#pragma unroll
            for (int nb = 0; nb < 2; nb++) {
                uint32_t boff = (uint32_t)(((b_row + nb * 16) * LQK + kk + b_col) * 2);
                uint32_t bh[4], bl[4];
                ldsm4(bh, uKhi + boff);
                ldsm4(bl, uKlo + boff);
                mma_bf16(sacc[nb * 2 + 0], qh, bh + 0);
                mma_bf16(sacc[nb * 2 + 1], qh, bh + 2);
                mma_bf16(sacc[nb * 2 + 0], qh, bl + 0);
                mma_bf16(sacc[nb * 2 + 1], qh, bl + 2);
                mma_bf16(sacc[nb * 2 + 0], ql, bh + 0);
                mma_bf16(sacc[nb * 2 + 1], ql, bh + 2);
            }
        }
        // store S frags to smem
        {
            const int er = lane >> 2, ec = (lane & 3) * 2;
            const int srow = wq * 16 + er;
#pragma unroll
            for (int j = 0; j < 4; j++) {
                int scol = wk * 32 + (j >> 1) * 16 + (j & 1) * 8 + ec;
                Ss[srow * LSS + scol]           = sacc[j][0];
                Ss[srow * LSS + scol + 1]       = sacc[j][1];
                Ss[(srow + 8) * LSS + scol]     = sacc[j][2];
                Ss[(srow + 8) * LSS + scol + 1] = sacc[j][3];
            }
        }
        __syncthreads();

        // ---- softmax (validated R1 logic) ----
        {
            const int* km = (const int*)(dsmem + AOFF_KM + s * 256u);
            float sf[4][4];
#pragma unroll
            for (int i = 0; i < 4; i++) {
                int qg = q0 + ty * 4 + i;
#pragma unroll
                for (int j = 0; j < 4; j++) {
                    int kg = t * ATK + tx * 4 + j;
                    bool ok = (km[tx * 4 + j] != 0) && (!causal || kg <= qg);
                    float sv = Ss[(ty * 4 + i) * LSS + tx * 4 + j];
                    sf[i][j] = ok ? sv * scale : -1e30f;
                }
            }
#pragma unroll
            for (int i = 0; i < 4; i++) {
                float tmax = fmaxf(fmaxf(sf[i][0], sf[i][1]), fmaxf(sf[i][2], sf[i][3]));
#pragma unroll
                for (int o = 8; o > 0; o >>= 1)
                    tmax = fmaxf(tmax, __shfl_xor_sync(0xffffffffu, tmax, o));
                float nm = fmaxf(mi[i], tmax);

                float p[4], rs = 0.f;
#pragma unroll
                for (int j = 0; j < 4; j++) {
                    p[j] = (sf[i][j] <= -1e29f) ? 0.f : __expf(sf[i][j] - nm);
                    rs += p[j];
                }
#pragma unroll
                for (int o = 8; o > 0; o >>= 1)
                    rs += __shfl_xor_sync(0xffffffffu, rs, o);

                float alpha = __expf(mi[i] - nm);
                li[i] = li[i] * alpha + rs;
                mi[i] = nm;
                sAl[ty * 4 + i] = alpha;

                // split P -> hi/lo bf16, store
                __nv_bfloat16 ph[4], pl[4];
#pragma unroll
                for (int j = 0; j < 4; j++) {
                    ph[j] = __float2bfloat16(p[j]);
                    pl[j] = __float2bfloat16(p[j] - __bfloat162float(ph[j]));
                }
                uint32_t poff = (uint32_t)(((ty * 4 + i) * LP + tx * 4) * 2);
                *(uint2*)(dsmem + AOFF_P + poff)        = *(uint2*)ph;
                *(uint2*)(dsmem + AOFF_P + 9216 + poff) = *(uint2*)pl;
            }
        }
        __syncthreads();

        // ---- O = O*alpha + P V (3-term) ----
        {
            const int er = lane >> 2;
            float a0 = sAl[wq * 16 + er];
            float a1 = sAl[wq * 16 + er + 8];
#pragma unroll
            for (int j = 0; j < 8; j++) {
                oacc[j][0] *= a0; oacc[j][1] *= a0;
                oacc[j][2] *= a1; oacc[j][3] *= a1;
            }
            const uint32_t uPhi = sb + AOFF_P;
            const uint32_t uPlo = sb + AOFF_P + 9216;
            const uint32_t uVhi = sb + AOFF_V + s * 34816u;
            const uint32_t uVlo = uVhi + 17408;
#pragma unroll
            for (int ks = 0; ks < 4; ks++) {
                const int kk = ks * 16;
                uint32_t ph[4], pl[4];
                uint32_t poff = (uint32_t)((a_row * LP + kk + a_col) * 2);
                ldsm4(ph, uPhi + poff);
                ldsm4(pl, uPlo + poff);
#pragma unroll
                for (int nb = 0; nb < 4; nb++) {
                    int d0 = wk * 64 + nb * 16;
                    uint32_t voff = (uint32_t)(((kk + vt_row) * LQK + d0 + vt_seg) * 2);
                    uint32_t vh[4], vl[4];
                    ldsm4t(vh, uVhi + voff);
                    ldsm4t(vl, uVlo + voff);
                    mma_bf16(oacc[nb * 2 + 0], ph, vh + 0);
                    mma_bf16(oacc[nb * 2 + 1], ph, vh + 2);
                    mma_bf16(oacc[nb * 2 + 0], ph, vl + 0);
                    mma_bf16(oacc[nb * 2 + 1], ph, vl + 2);
                    mma_bf16(oacc[nb * 2 + 0], pl, vh + 0);
                    mma_bf16(oacc[nb * 2 + 1], pl, vh + 2);
                }
            }
        }
        __syncthreads();   // PV done with V[s], P before next tile overwrites
    }

    // final 1/li
    sLi[ty * 4 + 0] = (li[0] > 0.f) ? 1.f / li[0] : 0.f;
    sLi[ty * 4 + 1] = (li[1] > 0.f) ? 1.f / li[1] : 0.f;
    sLi[ty * 4 + 2] = (li[2] > 0.f) ? 1.f / li[2] : 0.f;
    sLi[ty * 4 + 3] = (li[3] > 0.f) ? 1.f / li[3] : 0.f;
    __syncthreads();

    // write output hi/lo bf16
    {
        const int er = lane >> 2, ec = (lane & 3) * 2;
        float inv0 = sLi[wq * 16 + er];
        float inv1 = sLi[wq * 16 + er + 8];
        size_t grow0 = ((size_t)b * SS + q0 + wq * 16 + er) * 2048;
        size_t grow1 = grow0 + (size_t)8 * 2048;
#pragma unroll
        for (int j = 0; j < 8; j++) {
            size_t colg = (size_t)h * 128 + wk * 64 + j * 8 + ec;
            float v00 = oacc[j][0] * inv0, v01 = oacc[j][1] * inv0;
            float v10 = oacc[j][2] * inv1, v11 = oacc[j][3] * inv1;
            __nv_bfloat16 h00 = __float2bfloat16(v00);
            __nv_bfloat16 h01 = __float2bfloat16(v01);
            __nv_bfloat16 h10 = __float2bfloat16(v10);
            __nv_bfloat16 h11 = __float2bfloat16(v11);
            __nv_bfloat162 hi0; hi0.x = h00; hi0.y = h01;
            __nv_bfloat162 hi1; hi1.x = h10; hi1.y = h11;
            __nv_bfloat162 lo0;
            lo0.x = __float2bfloat16(v00 - __bfloat162float(h00));
            lo0.y = __float2bfloat16(v01 - __bfloat162float(h01));
            __nv_bfloat162 lo1;
            lo1.x = __float2bfloat16(v10 - __bfloat162float(h10));
            lo1.y = __float2bfloat16(v11 - __bfloat162float(h11));
            *(__nv_bfloat162*)(ohi + grow0 + colg) = hi0;
            *(__nv_bfloat162*)(olo + grow0 + colg) = lo0;
            *(__nv_bfloat162*)(ohi + grow1 + colg) = hi1;
            *(__nv_bfloat162*)(olo + grow1 + colg) = lo1;
        }
    }
}

// ---------------------------------------------------------------------------
// Launch
// ---------------------------------------------------------------------------
extern "C" void kernel_launch(void* const* d_in, const int* in_sizes, int n_in,
                              void* d_out, int out_size)
{
    const float* x_q    = (const float*)d_in[0];
    const float* x_kv   = (const float*)d_in[1];
    const float* Wq     = (const float*)d_in[2];
    const float* bq     = (const float*)d_in[3];
    const float* Wk     = (const float*)d_in[4];
    const float* bk     = (const float*)d_in[5];
    const float* Wv     = (const float*)d_in[6];
    const float* bv     = (const float*)d_in[7];
    const float* Wo     = (const float*)d_in[8];
    const float* bo     = (const float*)d_in[9];
    const float* angles = (const float*)d_in[10];
    const int*   amask  = (const int*)d_in[11];
    const int*   causal = (const int*)d_in[12];
    const int*   k_rope = (const int*)d_in[13];
    float* out = (float*)d_out;

    float *q, *k, *v;
    cudaGetSymbolAddress((void**)&q, g_q);
    cudaGetSymbolAddress((void**)&k, g_k);
    cudaGetSymbolAddress((void**)&v, g_v);

    __nv_bfloat16 *xq_hi, *xq_lo, *xkv_hi, *xkv_lo, *v_hi, *v_lo, *at_hi, *at_lo;
    __nv_bfloat16 *wq_hi, *wq_lo, *wk_hi, *wk_lo, *wv_hi, *wv_lo, *wo_hi, *wo_lo;
    cudaGetSymbolAddress((void**)&xq_hi,  g_xq_hi);
    cudaGetSymbolAddress((void**)&xq_lo,  g_xq_lo);
    cudaGetSymbolAddress((void**)&xkv_hi, g_xkv_hi);
    cudaGetSymbolAddress((void**)&xkv_lo, g_xkv_lo);
    cudaGetSymbolAddress((void**)&v_hi,   g_v_hi);
    cudaGetSymbolAddress((void**)&v_lo,   g_v_lo);
    cudaGetSymbolAddress((void**)&at_hi,  g_at_hi);
    cudaGetSymbolAddress((void**)&at_lo,  g_at_lo);
    cudaGetSymbolAddress((void**)&wq_hi,  g_wq_hi);
    cudaGetSymbolAddress((void**)&wq_lo,  g_wq_lo);
    cudaGetSymbolAddress((void**)&wk_hi,  g_wk_hi);
    cudaGetSymbolAddress((void**)&wk_lo,  g_wk_lo);
    cudaGetSymbolAddress((void**)&wv_hi,  g_wv_hi);
    cudaGetSymbolAddress((void**)&wv_lo,  g_wv_lo);
    cudaGetSymbolAddress((void**)&wo_hi,  g_wo_hi);
    cudaGetSymbolAddress((void**)&wo_lo,  g_wo_lo);

    const int M = MM, N = EE, K = EE;
    const int xBlocks = (int)(NELEM / 4 / 256);
    const int wBlocks = (int)(WELEM / 4 / 256);

    cudaFuncSetAttribute(gemm_bf16p_kernel,
                         cudaFuncAttributeMaxDynamicSharedMemorySize, GEMM_SMEM_BYTES);
    cudaFuncSetAttribute(attn_mma_kernel,
                         cudaFuncAttributeMaxDynamicSharedMemorySize, ATTN_SMEM_BYTES);
    dim3 gGrid(N / GBN, M / GBM);   // (16, 64)

    // input splits
    split_kernel<<<xBlocks, 256>>>(x_q,  xq_hi,  xq_lo,  NELEM / 4);
    split_kernel<<<xBlocks, 256>>>(x_kv, xkv_hi, xkv_lo, NELEM / 4);
    split_kernel<<<wBlocks, 256>>>(Wq, wq_hi, wq_lo, WELEM / 4);
    split_kernel<<<wBlocks, 256>>>(Wk, wk_hi, wk_lo, WELEM / 4);
    split_kernel<<<wBlocks, 256>>>(Wv, wv_hi, wv_lo, WELEM / 4);
    split_kernel<<<wBlocks, 256>>>(Wo, wo_hi, wo_lo, WELEM / 4);

    // projections (fp32 outputs for rope)
    gemm_bf16p_kernel<<<gGrid, 256, GEMM_SMEM_BYTES>>>(xq_hi,  xq_lo,  wq_hi, wq_lo, bq, q, M, N, K);
    gemm_bf16p_kernel<<<gGrid, 256, GEMM_SMEM_BYTES>>>(xkv_hi, xkv_lo, wk_hi, wk_lo, bk, k, M, N, K);
    gemm_bf16p_kernel<<<gGrid, 256, GEMM_SMEM_BYTES>>>(xkv_hi, xkv_lo, wv_hi, wv_lo, bv, v, M, N, K);

    size_t ropeTotal = (size_t)BB * SS * HH * DH;
    int ropeBlocks = (int)((ropeTotal + 255) / 256);
    rope_kernel<<<ropeBlocks, 256>>>(q, angles, k_rope, 1);
    rope_kernel<<<ropeBlocks, 256>>>(k, angles, k_rope, 0);

    // split q/k/v for attention (reuse xq/xkv buffers, now free)
    split_kernel<<<xBlocks, 256>>>(q, xq_hi,  xq_lo,  NELEM / 4);
    split_kernel<<<xBlocks, 256>>>(k, xkv_hi, xkv_lo, NELEM / 4);
    split_kernel<<<xBlocks, 256>>>(v, v_hi,   v_lo,   NELEM / 4);

    // attention (writes hi/lo directly)
    dim3 aGrid(BB * HH, SS / ATQ);   // (64, 32)
    attn_mma_kernel<<<aGrid, 256, ATTN_SMEM_BYTES>>>(
        xq_hi, xq_lo, xkv_hi, xkv_lo, v_hi, v_lo, amask, causal, at_hi, at_lo);

    // output projection
    gemm_bf16p_kernel<<<gGrid, 256, GEMM_SMEM_BYTES>>>(at_hi, at_lo, wo_hi, wo_lo, bo, out, M, N, K);
}

// round 10
// speedup vs baseline: 2.0164x; 1.0133x over previous
#include <cuda_runtime.h>
#include <cuda_bf16.h>
#include <cstdint>
#include <math.h>

// Problem constants
#define BB 4
#define SS 2048
#define EE 2048
#define HH 16
#define DD 128
#define DH 64   // DD/2

#define MM (BB * SS)              // 8192
#define NELEM ((size_t)MM * EE)   // 16,777,216
#define WELEM ((size_t)EE * EE)   // 4,194,304

// ---------------------------------------------------------------------------
// Scratch (device globals — no allocation allowed in kernel_launch)
// ---------------------------------------------------------------------------
__device__ float g_q[NELEM];
__device__ float g_k[NELEM];

__device__ __nv_bfloat16 g_xq_hi[NELEM],  g_xq_lo[NELEM];   // later reused: q hi/lo
__device__ __nv_bfloat16 g_xkv_hi[NELEM], g_xkv_lo[NELEM];  // later reused: k hi/lo
__device__ __nv_bfloat16 g_v_hi[NELEM],   g_v_lo[NELEM];    // v hi/lo
__device__ __nv_bfloat16 g_at_hi[NELEM],  g_at_lo[NELEM];   // attn output hi/lo
__device__ __nv_bfloat16 g_wq_hi[WELEM], g_wq_lo[WELEM];
__device__ __nv_bfloat16 g_wk_hi[WELEM], g_wk_lo[WELEM];
__device__ __nv_bfloat16 g_wv_hi[WELEM], g_wv_lo[WELEM];
__device__ __nv_bfloat16 g_wo_hi[WELEM], g_wo_lo[WELEM];

// ---------------------------------------------------------------------------
// helpers
// ---------------------------------------------------------------------------
__device__ __forceinline__ uint32_t smem_u32(const void* p) {
    uint32_t a;
    asm("{ .reg .u64 t; cvta.to.shared.u64 t, %1; cvt.u32.u64 %0, t; }"
        : "=r"(a) : "l"(p));
    return a;
}

__device__ __forceinline__ void ldsm4(uint32_t* r, uint32_t addr) {
    asm volatile("ldmatrix.sync.aligned.m8n8.x4.shared.b16 {%0,%1,%2,%3}, [%4];"
        : "=r"(r[0]), "=r"(r[1]), "=r"(r[2]), "=r"(r[3]) : "r"(addr));
}

__device__ __forceinline__ void ldsm4t(uint32_t* r, uint32_t addr) {
    asm volatile("ldmatrix.sync.aligned.m8n8.x4.trans.shared.b16 {%0,%1,%2,%3}, [%4];"
        : "=r"(r[0]), "=r"(r[1]), "=r"(r[2]), "=r"(r[3]) : "r"(addr));
}

__device__ __forceinline__ void mma_bf16(float* d, const uint32_t* a,
                                         const uint32_t* b) {
    asm volatile(
        "mma.sync.aligned.m16n8k16.row.col.f32.bf16.bf16.f32 "
        "{%0,%1,%2,%3}, {%4,%5,%6,%7}, {%8,%9}, {%0,%1,%2,%3};"
        : "+f"(d[0]), "+f"(d[1]), "+f"(d[2]), "+f"(d[3])
        : "r"(a[0]), "r"(a[1]), "r"(a[2]), "r"(a[3]), "r"(b[0]), "r"(b[1]));
}

__device__ __forceinline__ void cp16(uint32_t dst, const void* src) {
    asm volatile("cp.async.ca.shared.global [%0], [%1], 16;"
        :: "r"(dst), "l"((uint64_t)__cvta_generic_to_global(src)));
}
#define CP_COMMIT() asm volatile("cp.async.commit_group;")
#define CP_WAIT(n)  asm volatile("cp.async.wait_group %0;" :: "n"(n))

// ---------------------------------------------------------------------------
// Split fp32 -> (hi, lo) bf16 pair
// ---------------------------------------------------------------------------
__global__ __launch_bounds__(256) void split_kernel(
    const float* __restrict__ src, __nv_bfloat16* __restrict__ hi,
    __nv_bfloat16* __restrict__ lo, size_t n4)
{
    size_t i = (size_t)blockIdx.x * blockDim.x + threadIdx.x;
    if (i >= n4) return;
    float4 v = *(const float4*)(src + i * 4);
    __nv_bfloat16 h[4], l[4];
    const float* f = (const float*)&v;
#pragma unroll
    for (int e = 0; e < 4; e++) {
        h[e] = __float2bfloat16(f[e]);
        l[e] = __float2bfloat16(f[e] - __bfloat162float(h[e]));
    }
    *(uint2*)(hi + i * 4) = *(uint2*)h;
    *(uint2*)(lo + i * 4) = *(uint2*)l;
}

// ---------------------------------------------------------------------------
// Fused RoPE + split: reads fp32 [B,S,H,D], writes bf16 hi/lo pair.
// Applies rotation iff (always || *flag). angles: [2][S][DH] (0=sin, 1=cos).
// ---------------------------------------------------------------------------
__global__ __launch_bounds__(256) void rope_split_kernel(
    const float* __restrict__ x, const float* __restrict__ angles,
    const int* __restrict__ flag, int always,
    __nv_bfloat16* __restrict__ hi, __nv_bfloat16* __restrict__ lo)
{
    size_t i = (size_t)blockIdx.x * blockDim.x + threadIdx.x;
    const size_t total = (size_t)BB * SS * HH * DH;
    if (i >= total) return;
    const bool doRope = always || (*flag != 0);
    int half = (int)(i % DH);
    int h    = (int)((i / DH) % HH);
    int s    = (int)((i / ((size_t)DH * HH)) % SS);
    int b    = (int)(i / ((size_t)DH * HH * SS));

    size_t base = (((size_t)b * SS + s) * HH + h) * (size_t)DD;
    float x1 = x[base + half];
    float x2 = x[base + DH + half];
    float y1 = x1, y2 = x2;
    if (doRope) {
        float sn = angles[(size_t)s * DH + half];
        float cs = angles[(size_t)SS * DH + (size_t)s * DH + half];
        y1 = x1 * cs - x2 * sn;
        y2 = x1 * sn + x2 * cs;
    }
    __nv_bfloat16 h1 = __float2bfloat16(y1);
    __nv_bfloat16 h2 = __float2bfloat16(y2);
    hi[base + half]      = h1;
    hi[base + DH + half] = h2;
    lo[base + half]      = __float2bfloat16(y1 - __bfloat162float(h1));
    lo[base + DH + half] = __float2bfloat16(y2 - __bfloat162float(h2));
}

// ---------------------------------------------------------------------------
// Pre-split bf16 tensor-core GEMM (R7 config, VALIDATED): C = A @ W^T + bias
// CTA 128x128, BK=32, 2-stage cp.async, 8 warps, 2 CTAs/SM.
// Epilogue writes fp32 C (if non-null) and/or bf16 hi/lo pair (if non-null).
// ---------------------------------------------------------------------------
#define GBM 128
#define GBN 128
#define GBK 32
#define LDS 40
#define BUFB (GBM * LDS * 2)       // 10240 bytes per buffer
#define GEMM_SMEM_BYTES (BUFB * 8)

__global__ __launch_bounds__(256) void gemm_bf16p_kernel(
    const __nv_bfloat16* __restrict__ Ahi, const __nv_bfloat16* __restrict__ Alo,
    const __nv_bfloat16* __restrict__ Bhi, const __nv_bfloat16* __restrict__ Blo,
    const float* __restrict__ bias, float* __restrict__ C,
    __nv_bfloat16* __restrict__ Chi, __nv_bfloat16* __restrict__ Clo,
    int M, int N, int K)
{
    extern __shared__ __align__(16) char dsmem[];
    const uint32_t sb = smem_u32(dsmem);

    const int tid  = threadIdx.x;
    const int lane = tid & 31;
    const int wid  = tid >> 5;
    const int wm   = wid & 3;
    const int wn   = wid >> 2;
    const size_t m0 = (size_t)blockIdx.y * GBM;
    const size_t n0 = (size_t)blockIdx.x * GBN;

    float acc[2][8][4];
#pragma unroll
    for (int i = 0; i < 2; i++)
#pragma unroll
        for (int j = 0; j < 8; j++)
#pragma unroll
            for (int e = 0; e < 4; e++) acc[i][j][e] = 0.f;

    const int seg0 = tid * 2;
    const int r0 = seg0 >> 2,        cs0 = seg0 & 3;
    const int r1 = (seg0 + 1) >> 2,  cs1 = (seg0 + 1) & 3;

    const int a_row = wm * 32 + (lane & 15);
    const int a_col = (lane >> 4) << 3;
    const int b_row = wn * 64 + ((lane >> 4) << 3) + (lane & 7);
    const int b_col = ((lane >> 3) & 1) << 3;

    const int nChunks = K / GBK;

#define PREFETCH(c, s) do {                                                     \
    size_t ca = (size_t)(c) * GBK;                                              \
    uint32_t d0 = (uint32_t)(r0 * 80 + cs0 * 16);                               \
    uint32_t d1 = (uint32_t)(r1 * 80 + cs1 * 16);                               \
    cp16(sb + (0 + (s)) * BUFB + d0, Ahi + (m0 + r0) * K + ca + cs0 * 8);       \
    cp16(sb + (0 + (s)) * BUFB + d1, Ahi + (m0 + r1) * K + ca + cs1 * 8);       \
    cp16(sb + (2 + (s)) * BUFB + d0, Alo + (m0 + r0) * K + ca + cs0 * 8);       \
    cp16(sb + (2 + (s)) * BUFB + d1, Alo + (m0 + r1) * K + ca + cs1 * 8);       \
    cp16(sb + (4 + (s)) * BUFB + d0, Bhi + (n0 + r0) * K + ca + cs0 * 8);       \
    cp16(sb + (4 + (s)) * BUFB + d1, Bhi + (n0 + r1) * K + ca + cs1 * 8);       \
    cp16(sb + (6 + (s)) * BUFB + d0, Blo + (n0 + r0) * K + ca + cs0 * 8);       \
    cp16(sb + (6 + (s)) * BUFB + d1, Blo + (n0 + r1) * K + ca + cs1 * 8);       \
} while (0)

    PREFETCH(0, 0);
    CP_COMMIT();

    for (int c = 0; c < nChunks; c++) {
        const int s = c & 1;
        if (c + 1 < nChunks) {
            PREFETCH(c + 1, s ^ 1);
            CP_COMMIT();
            CP_WAIT(1);
        } else {
            CP_WAIT(0);
        }
        __syncthreads();

        const uint32_t uAhi = sb + (0 + s) * BUFB;
        const uint32_t uAlo = sb + (2 + s) * BUFB;
        const uint32_t uBhi = sb + (4 + s) * BUFB;
        const uint32_t uBlo = sb + (6 + s) * BUFB;

#pragma unroll
        for (int ks = 0; ks < 2; ks++) {
            const int kk = ks * 16;
            uint32_t ahi[2][4], alo[2][4];
#pragma unroll
            for (int mi = 0; mi < 2; mi++) {
                uint32_t aoff = (uint32_t)(((a_row + mi * 16) * LDS + kk + a_col) * 2);
                ldsm4(ahi[mi], uAhi + aoff);
                ldsm4(alo[mi], uAlo + aoff);
            }
#pragma unroll
            for (int nb = 0; nb < 4; nb++) {
                uint32_t boff = (uint32_t)(((b_row + nb * 16) * LDS + kk + b_col) * 2);
                uint32_t bh[4], bl[4];
                ldsm4(bh, uBhi + boff);
                ldsm4(bl, uBlo + boff);
#pragma unroll
                for (int mi = 0; mi < 2; mi++) {
                    mma_bf16(acc[mi][nb * 2 + 0], ahi[mi], bh + 0);
                    mma_bf16(acc[mi][nb * 2 + 1], ahi[mi], bh + 2);
                    mma_bf16(acc[mi][nb * 2 + 0], ahi[mi], bl + 0);
                    mma_bf16(acc[mi][nb * 2 + 1], ahi[mi], bl + 2);
                    mma_bf16(acc[mi][nb * 2 + 0], alo[mi], bh + 0);
                    mma_bf16(acc[mi][nb * 2 + 1], alo[mi], bh + 2);
                }
            }
        }
        __syncthreads();
    }

    const int er = lane >> 2;
    const int ec = (lane & 3) * 2;
#pragma unroll
    for (int mi = 0; mi < 2; mi++) {
#pragma unroll
        for (int nbb = 0; nbb < 8; nbb++) {
            size_t row0 = m0 + wm * 32 + mi * 16 + er;
            size_t col  = n0 + wn * 64 + nbb * 8 + ec;
            float b0 = __ldg(bias + col);
            float b1 = __ldg(bias + col + 1);
            float v00 = acc[mi][nbb][0] + b0, v01 = acc[mi][nbb][1] + b1;
            float v10 = acc[mi][nbb][2] + b0, v11 = acc[mi][nbb][3] + b1;
            if (C) {
                *(float2*)(C + row0 * (size_t)N + col)       = make_float2(v00, v01);
                *(float2*)(C + (row0 + 8) * (size_t)N + col) = make_float2(v10, v11);
            }
            if (Chi) {
                __nv_bfloat16 h00 = __float2bfloat16(v00);
                __nv_bfloat16 h01 = __float2bfloat16(v01);
                __nv_bfloat16 h10 = __float2bfloat16(v10);
                __nv_bfloat16 h11 = __float2bfloat16(v11);
                __nv_bfloat162 hi0; hi0.x = h00; hi0.y = h01;
                __nv_bfloat162 hi1; hi1.x = h10; hi1.y = h11;
                __nv_bfloat162 lo0;
                lo0.x = __float2bfloat16(v00 - __bfloat162float(h00));
                lo0.y = __float2bfloat16(v01 - __bfloat162float(h01));
                __nv_bfloat162 lo1;
                lo1.x = __float2bfloat16(v10 - __bfloat162float(h10));
                lo1.y = __float2bfloat16(v11 - __bfloat162float(h11));
                *(__nv_bfloat162*)(Chi + row0 * (size_t)N + col)       = hi0;
                *(__nv_bfloat162*)(Clo + row0 * (size_t)N + col)       = lo0;
                *(__nv_bfloat162*)(Chi + (row0 + 8) * (size_t)N + col) = hi1;
                *(__nv_bfloat162*)(Clo + (row0 + 8) * (size_t)N + col) = lo1;
            }
        }
    }
}

// ---------------------------------------------------------------------------
// Flash attention with 3-term split-bf16 mma.sync (VALIDATED R9).
// ---------------------------------------------------------------------------
#define ATQ 64
#define ATK 64
#define LQK 136
#define LP  72
#define LSS 68

#define AOFF_Q   0u
#define AOFF_K   34816u
#define AOFF_V   104448u
#define AOFF_S   174080u
#define AOFF_P   191488u
#define AOFF_AL  209920u
#define AOFF_LI  210176u
#define AOFF_KM  210432u
#define ATTN_SMEM_BYTES 210944

__global__ __launch_bounds__(256, 1) void attn_mma_kernel(
    const __nv_bfloat16* __restrict__ qhi, const __nv_bfloat16* __restrict__ qlo,
    const __nv_bfloat16* __restrict__ khi, const __nv_bfloat16* __restrict__ klo,
    const __nv_bfloat16* __restrict__ vhi, const __nv_bfloat16* __restrict__ vlo,
    const int* __restrict__ amask, const int* __restrict__ causal_ptr,
    __nv_bfloat16* __restrict__ ohi, __nv_bfloat16* __restrict__ olo)
{
    extern __shared__ __align__(16) char dsmem[];
    const uint32_t sb = smem_u32(dsmem);
    float* Ss    = (float*)(dsmem + AOFF_S);
    float* sAl   = (float*)(dsmem + AOFF_AL);
    float* sLi   = (float*)(dsmem + AOFF_LI);

    const int tid  = threadIdx.x;
    const int lane = tid & 31;
    const int wid  = tid >> 5;
    const int wq   = wid & 3;
    const int wk   = wid >> 2;
    const int b  = blockIdx.x >> 4;
    const int h  = blockIdx.x & 15;
    const int q0 = blockIdx.y * ATQ;
    const int causal = *causal_ptr;

    const int ty = tid >> 4;
    const int tx = tid & 15;
    const float scale = 0.0883883476483184f;   // 1/sqrt(128)

    const int a_row = wq * 16 + (lane & 15);
    const int a_col = (lane >> 4) << 3;
    const int b_row = wk * 32 + ((lane >> 4) << 3) + (lane & 7);
    const int b_col = ((lane >> 3) & 1) << 3;
    const int vt_row = lane & 15;
    const int vt_seg = (lane >> 4) << 3;

    const size_t gq = ((size_t)b * SS + q0) * 2048 + (size_t)h * 128;
#pragma unroll
    for (int it = 0; it < 4; it++) {
        int i = tid + it * 256;
        int r = i >> 4, sg = i & 15;
        uint32_t off = (uint32_t)(r * 272 + sg * 16);
        cp16(sb + AOFF_Q + off,         qhi + gq + (size_t)r * 2048 + sg * 8);
        cp16(sb + AOFF_Q + 17408 + off, qlo + gq + (size_t)r * 2048 + sg * 8);
    }

#define PREFETCH_KV(t, s) do {                                                   \
    size_t gk = ((size_t)b * SS + (size_t)(t) * ATK) * 2048 + (size_t)h * 128;   \
    for (int it = 0; it < 4; it++) {                                             \
        int i = tid + it * 256;                                                  \
        int r = i >> 4, sg = i & 15;                                             \
        uint32_t off = (uint32_t)(r * 272 + sg * 16);                            \
        size_t go = (size_t)r * 2048 + sg * 8;                                   \
        cp16(sb + AOFF_K + (s) * 34816u + off,          khi + gk + go);          \
        cp16(sb + AOFF_K + (s) * 34816u + 17408 + off,  klo + gk + go);          \
        cp16(sb + AOFF_V + (s) * 34816u + off,          vhi + gk + go);          \
        cp16(sb + AOFF_V + (s) * 34816u + 17408 + off,  vlo + gk + go);          \
    }                                                                            \
    if (tid < 16)                                                                \
        cp16(sb + AOFF_KM + (s) * 256u + tid * 16,                               \
             amask + (size_t)b * SS + (size_t)(t) * ATK + tid * 4);              \
} while (0)

    float oacc[8][4];
#pragma unroll
    for (int j = 0; j < 8; j++)
#pragma unroll
        for (int e = 0; e < 4; e++) oacc[j][e] = 0.f;
    float mi[4], li[4];
#pragma unroll
    for (int i = 0; i < 4; i++) { mi[i] = -1e30f; li[i] = 0.f; }

    PREFETCH_KV(0, 0);
    CP_COMMIT();

    const int nTiles = SS / ATK;   // 32
    for (int t = 0; t < nTiles; t++) {
        const int s = t & 1;
        if (t + 1 < nTiles) {
            PREFETCH_KV(t + 1, s ^ 1);
            CP_COMMIT();
            CP_WAIT(1);
        } else {
            CP_WAIT(0);
        }
        __syncthreads();

        // ---- S = Q K^T (3-term) ----
        const uint32_t uQhi = sb + AOFF_Q;
        const uint32_t uQlo = sb + AOFF_Q + 17408;
        const uint32_t uKhi = sb + AOFF_K + s * 34816u;
        const uint32_t uKlo = uKhi + 17408;

        float sacc[4][4];
#pragma unroll
        for (int j = 0; j < 4; j++)
#pragma unroll
            for (int e = 0; e < 4; e++) sacc[j][e] = 0.f;

#pragma unroll
        for (int ks = 0; ks < 8; ks++) {
            const int kk = ks * 16;
            uint32_t qh[4], ql[4];
            uint32_t aoff = (uint32_t)((a_row * LQK + kk + a_col) * 2);
            ldsm4(qh, uQhi + aoff);
            ldsm4(ql, uQlo + aoff);
#pragma unroll
            for (int nb = 0; nb < 2; nb++) {
                uint32_t boff = (uint32_t)(((b_row + nb * 16) * LQK + kk + b_col) * 2);
                uint32_t bh[4], bl[4];
                ldsm4(bh, uKhi + boff);
                ldsm4(bl, uKlo + boff);
                mma_bf16(sacc[nb * 2 + 0], qh, bh + 0);
                mma_bf16(sacc[nb * 2 + 1], qh, bh + 2);
                mma_bf16(sacc[nb * 2 + 0], qh, bl + 0);
                mma_bf16(sacc[nb * 2 + 1], qh, bl + 2);
                mma_bf16(sacc[nb * 2 + 0], ql, bh + 0);
                mma_bf16(sacc[nb * 2 + 1], ql, bh + 2);
            }
        }
        {
            const int er = lane >> 2, ec = (lane & 3) * 2;
            const int srow = wq * 16 + er;
#pragma unroll
            for (int j = 0; j < 4; j++) {
                int scol = wk * 32 + (j >> 1) * 16 + (j & 1) * 8 + ec;
                Ss[srow * LSS + scol]           = sacc[j][0];
                Ss[srow * LSS + scol + 1]       = sacc[j][1];
                Ss[(srow + 8) * LSS + scol]     = sacc[j][2];
                Ss[(srow + 8) * LSS + scol + 1] = sacc[j][3];
            }
        }
        __syncthreads();

        // ---- softmax ----
        {
            const int* km = (const int*)(dsmem + AOFF_KM + s * 256u);
            float sf[4][4];
#pragma unroll
            for (int i = 0; i < 4; i++) {
                int qg = q0 + ty * 4 + i;
#pragma unroll
                for (int j = 0; j < 4; j++) {
                    int kg = t * ATK + tx * 4 + j;
                    bool ok = (km[tx * 4 + j] != 0) && (!causal || kg <= qg);
                    float sv = Ss[(ty * 4 + i) * LSS + tx * 4 + j];
                    sf[i][j] = ok ? sv * scale : -1e30f;
                }
            }
#pragma unroll
            for (int i = 0; i < 4; i++) {
                float tmax = fmaxf(fmaxf(sf[i][0], sf[i][1]), fmaxf(sf[i][2], sf[i][3]));
#pragma unroll
                for (int o = 8; o > 0; o >>= 1)
                    tmax = fmaxf(tmax, __shfl_xor_sync(0xffffffffu, tmax, o));
                float nm = fmaxf(mi[i], tmax);

                float p[4], rs = 0.f;
#pragma unroll
                for (int j = 0; j < 4; j++) {
                    p[j] = (sf[i][j] <= -1e29f) ? 0.f : __expf(sf[i][j] - nm);
                    rs += p[j];
                }
#pragma unroll
                for (int o = 8; o > 0; o >>= 1)
                    rs += __shfl_xor_sync(0xffffffffu, rs, o);

                float alpha = __expf(mi[i] - nm);
                li[i] = li[i] * alpha + rs;
                mi[i] = nm;
                sAl[ty * 4 + i] = alpha;

                __nv_bfloat16 ph[4], pl[4];
#pragma unroll
                for (int j = 0; j < 4; j++) {
                    ph[j] = __float2bfloat16(p[j]);
                    pl[j] = __float2bfloat16(p[j] - __bfloat162float(ph[j]));
                }
                uint32_t poff = (uint32_t)(((ty * 4 + i) * LP + tx * 4) * 2);
                *(uint2*)(dsmem + AOFF_P + poff)        = *(uint2*)ph;
                *(uint2*)(dsmem + AOFF_P + 9216 + poff) = *(uint2*)pl;
            }
        }
        __syncthreads();

        // ---- O = O*alpha + P V (3-term) ----
        {
            const int er = lane >> 2;
            float a0 = sAl[wq * 16 + er];
            float a1 = sAl[wq * 16 + er + 8];
#pragma unroll
            for (int j = 0; j < 8; j++) {
                oacc[j][0] *= a0; oacc[j][1] *= a0;
                oacc[j][2] *= a1; oacc[j][3] *= a1;
            }
            const uint32_t uPhi = sb + AOFF_P;
            const uint32_t uPlo = sb + AOFF_P + 9216;
            const uint32_t uVhi = sb + AOFF_V + s * 34816u;
            const uint32_t uVlo = uVhi + 17408;
#pragma unroll
            for (int ks = 0; ks < 4; ks++) {
                const int kk = ks * 16;
                uint32_t ph[4], pl[4];
                uint32_t poff = (uint32_t)((a_row * LP + kk + a_col) * 2);
                ldsm4(ph, uPhi + poff);
                ldsm4(pl, uPlo + poff);
#pragma unroll
                for (int nb = 0; nb < 4; nb++) {
                    int d0 = wk * 64 + nb * 16;
                    uint32_t voff = (uint32_t)(((kk + vt_row) * LQK + d0 + vt_seg) * 2);
                    uint32_t vh[4], vl[4];
                    ldsm4t(vh, uVhi + voff);
                    ldsm4t(vl, uVlo + voff);
                    mma_bf16(oacc[nb * 2 + 0], ph, vh + 0);
                    mma_bf16(oacc[nb * 2 + 1], ph, vh + 2);
                    mma_bf16(oacc[nb * 2 + 0], ph, vl + 0);
                    mma_bf16(oacc[nb * 2 + 1], ph, vl + 2);
                    mma_bf16(oacc[nb * 2 + 0], pl, vh + 0);
                    mma_bf16(oacc[nb * 2 + 1], pl, vh + 2);
                }
            }
        }
        __syncthreads();
    }

    sLi[ty * 4 + 0] = (li[0] > 0.f) ? 1.f / li[0] : 0.f;
    sLi[ty * 4 + 1] = (li[1] > 0.f) ? 1.f / li[1] : 0.f;
    sLi[ty * 4 + 2] = (li[2] > 0.f) ? 1.f / li[2] : 0.f;
    sLi[ty * 4 + 3] = (li[3] > 0.f) ? 1.f / li[3] : 0.f;
    __syncthreads();

    {
        const int er = lane >> 2, ec = (lane & 3) * 2;
        float inv0 = sLi[wq * 16 + er];
        float inv1 = sLi[wq * 16 + er + 8];
        size_t grow0 = ((size_t)b * SS + q0 + wq * 16 + er) * 2048;
        size_t grow1 = grow0 + (size_t)8 * 2048;
#pragma unroll
        for (int j = 0; j < 8; j++) {
            size_t colg = (size_t)h * 128 + wk * 64 + j * 8 + ec;
            float v00 = oacc[j][0] * inv0, v01 = oacc[j][1] * inv0;
            float v10 = oacc[j][2] * inv1, v11 = oacc[j][3] * inv1;
            __nv_bfloat16 h00 = __float2bfloat16(v00);
            __nv_bfloat16 h01 = __float2bfloat16(v01);
            __nv_bfloat16 h10 = __float2bfloat16(v10);
            __nv_bfloat16 h11 = __float2bfloat16(v11);
            __nv_bfloat162 hi0; hi0.x = h00; hi0.y = h01;
            __nv_bfloat162 hi1; hi1.x = h10; hi1.y = h11;
            __nv_bfloat162 lo0;
            lo0.x = __float2bfloat16(v00 - __bfloat162float(h00));
            lo0.y = __float2bfloat16(v01 - __bfloat162float(h01));
            __nv_bfloat162 lo1;
            lo1.x = __float2bfloat16(v10 - __bfloat162float(h10));
            lo1.y = __float2bfloat16(v11 - __bfloat162float(h11));
            *(__nv_bfloat162*)(ohi + grow0 + colg) = hi0;
            *(__nv_bfloat162*)(olo + grow0 + colg) = lo0;
            *(__nv_bfloat162*)(ohi + grow1 + colg) = hi1;
            *(__nv_bfloat162*)(olo + grow1 + colg) = lo1;
        }
    }
}

// ---------------------------------------------------------------------------
// Launch  (order: 5 splits, then GEMM-Q as launch #6 for ncu -s 5 -c 1)
// ---------------------------------------------------------------------------
extern "C" void kernel_launch(void* const* d_in, const int* in_sizes, int n_in,
                              void* d_out, int out_size)
{
    const float* x_q    = (const float*)d_in[0];
    const float* x_kv   = (const float*)d_in[1];
    const float* Wq     = (const float*)d_in[2];
    const float* bq     = (const float*)d_in[3];
    const float* Wk     = (const float*)d_in[4];
    const float* bk     = (const float*)d_in[5];
    const float* Wv     = (const float*)d_in[6];
    const float* bv     = (const float*)d_in[7];
    const float* Wo     = (const float*)d_in[8];
    const float* bo     = (const float*)d_in[9];
    const float* angles = (const float*)d_in[10];
    const int*   amask  = (const int*)d_in[11];
    const int*   causal = (const int*)d_in[12];
    const int*   k_rope = (const int*)d_in[13];
    float* out = (float*)d_out;

    float *q, *k;
    cudaGetSymbolAddress((void**)&q, g_q);
    cudaGetSymbolAddress((void**)&k, g_k);

    __nv_bfloat16 *xq_hi, *xq_lo, *xkv_hi, *xkv_lo, *v_hi, *v_lo, *at_hi, *at_lo;
    __nv_bfloat16 *wq_hi, *wq_lo, *wk_hi, *wk_lo, *wv_hi, *wv_lo, *wo_hi, *wo_lo;
    cudaGetSymbolAddress((void**)&xq_hi,  g_xq_hi);
    cudaGetSymbolAddress((void**)&xq_lo,  g_xq_lo);
    cudaGetSymbolAddress((void**)&xkv_hi, g_xkv_hi);
    cudaGetSymbolAddress((void**)&xkv_lo, g_xkv_lo);
    cudaGetSymbolAddress((void**)&v_hi,   g_v_hi);
    cudaGetSymbolAddress((void**)&v_lo,   g_v_lo);
    cudaGetSymbolAddress((void**)&at_hi,  g_at_hi);
    cudaGetSymbolAddress((void**)&at_lo,  g_at_lo);
    cudaGetSymbolAddress((void**)&wq_hi,  g_wq_hi);
    cudaGetSymbolAddress((void**)&wq_lo,  g_wq_lo);
    cudaGetSymbolAddress((void**)&wk_hi,  g_wk_hi);
    cudaGetSymbolAddress((void**)&wk_lo,  g_wk_lo);
    cudaGetSymbolAddress((void**)&wv_hi,  g_wv_hi);
    cudaGetSymbolAddress((void**)&wv_lo,  g_wv_lo);
    cudaGetSymbolAddress((void**)&wo_hi,  g_wo_hi);
    cudaGetSymbolAddress((void**)&wo_lo,  g_wo_lo);

    const int M = MM, N = EE, K = EE;
    const int xBlocks = (int)(NELEM / 4 / 256);
    const int wBlocks = (int)(WELEM / 4 / 256);

    cudaFuncSetAttribute(gemm_bf16p_kernel,
                         cudaFuncAttributeMaxDynamicSharedMemorySize, GEMM_SMEM_BYTES);
    cudaFuncSetAttribute(attn_mma_kernel,
                         cudaFuncAttributeMaxDynamicSharedMemorySize, ATTN_SMEM_BYTES);
    dim3 gGrid(N / GBN, M / GBM);   // (16, 64)

    // launches 1-5: input splits needed for first GEMM
    split_kernel<<<xBlocks, 256>>>(x_q,  xq_hi,  xq_lo,  NELEM / 4);
    split_kernel<<<xBlocks, 256>>>(x_kv, xkv_hi, xkv_lo, NELEM / 4);
    split_kernel<<<wBlocks, 256>>>(Wq, wq_hi, wq_lo, WELEM / 4);
    split_kernel<<<wBlocks, 256>>>(Wk, wk_hi, wk_lo, WELEM / 4);
    split_kernel<<<wBlocks, 256>>>(Wv, wv_hi, wv_lo, WELEM / 4);
    // launch 6: profiled by ncu (-s 5 -c 1)
    gemm_bf16p_kernel<<<gGrid, 256, GEMM_SMEM_BYTES>>>(
        xq_hi,  xq_lo,  wq_hi, wq_lo, bq, q, nullptr, nullptr, M, N, K);
    gemm_bf16p_kernel<<<gGrid, 256, GEMM_SMEM_BYTES>>>(
        xkv_hi, xkv_lo, wk_hi, wk_lo, bk, k, nullptr, nullptr, M, N, K);
    // V: write hi/lo directly — no fp32 V, no split-V
    gemm_bf16p_kernel<<<gGrid, 256, GEMM_SMEM_BYTES>>>(
        xkv_hi, xkv_lo, wv_hi, wv_lo, bv, nullptr, v_hi, v_lo, M, N, K);
    split_kernel<<<wBlocks, 256>>>(Wo, wo_hi, wo_lo, WELEM / 4);

    // fused rope + split (q always; k gated on device flag); reuse xq/xkv bufs
    size_t ropeTotal = (size_t)BB * SS * HH * DH;
    int ropeBlocks = (int)((ropeTotal + 255) / 256);
    rope_split_kernel<<<ropeBlocks, 256>>>(q, angles, k_rope, 1, xq_hi,  xq_lo);
    rope_split_kernel<<<ropeBlocks, 256>>>(k, angles, k_rope, 0, xkv_hi, xkv_lo);

    // attention (writes hi/lo directly)
    dim3 aGrid(BB * HH, SS / ATQ);   // (64, 32)
    attn_mma_kernel<<<aGrid, 256, ATTN_SMEM_BYTES>>>(
        xq_hi, xq_lo, xkv_hi, xkv_lo, v_hi, v_lo, amask, causal, at_hi, at_lo);

    // output projection
    gemm_bf16p_kernel<<<gGrid, 256, GEMM_SMEM_BYTES>>>(
        at_hi, at_lo, wo_hi, wo_lo, bo, out, nullptr, nullptr, M, N, K);
}

// round 11
// speedup vs baseline: 2.6106x; 1.2947x over previous
#include <cuda_runtime.h>
#include <cuda_bf16.h>
#include <cstdint>
#include <math.h>

// Problem constants
#define BB 4
#define SS 2048
#define EE 2048
#define HH 16
#define DD 128
#define DH 64   // DD/2

#define MM (BB * SS)              // 8192
#define NELEM ((size_t)MM * EE)   // 16,777,216
#define WELEM ((size_t)EE * EE)   // 4,194,304

// ---------------------------------------------------------------------------
// Scratch (device globals — no allocation allowed in kernel_launch)
// ---------------------------------------------------------------------------
__device__ float g_q[NELEM];
__device__ float g_k[NELEM];
__device__ float g_attn[NELEM];

__device__ char g_xq_h[NELEM],  g_xq_l[NELEM];
__device__ char g_xkv_h[NELEM], g_xkv_l[NELEM];
__device__ char g_at_h[NELEM],  g_at_l[NELEM];
__device__ char g_wq_h[WELEM], g_wq_l[WELEM];
__device__ char g_wk_h[WELEM], g_wk_l[WELEM];
__device__ char g_wv_h[WELEM], g_wv_l[WELEM];
__device__ char g_wo_h[WELEM], g_wo_l[WELEM];
__device__ float g_sxq[MM], g_sxkv[MM], g_sat[MM];
__device__ float g_swq[EE], g_swk[EE], g_swv[EE], g_swo[EE];

__device__ __nv_bfloat16 g_qhi[NELEM], g_qlo[NELEM];
__device__ __nv_bfloat16 g_khi[NELEM], g_klo[NELEM];
__device__ __nv_bfloat16 g_vhi[NELEM], g_vlo[NELEM];

// ---------------------------------------------------------------------------
// helpers
// ---------------------------------------------------------------------------
__device__ __forceinline__ uint32_t smem_u32(const void* p) {
    uint32_t a;
    asm("{ .reg .u64 t; cvta.to.shared.u64 t, %1; cvt.u32.u64 %0, t; }"
        : "=r"(a) : "l"(p));
    return a;
}

__device__ __forceinline__ void ldsm4(uint32_t* r, uint32_t addr) {
    asm volatile("ldmatrix.sync.aligned.m8n8.x4.shared.b16 {%0,%1,%2,%3}, [%4];"
        : "=r"(r[0]), "=r"(r[1]), "=r"(r[2]), "=r"(r[3]) : "r"(addr));
}

__device__ __forceinline__ void ldsm4t(uint32_t* r, uint32_t addr) {
    asm volatile("ldmatrix.sync.aligned.m8n8.x4.trans.shared.b16 {%0,%1,%2,%3}, [%4];"
        : "=r"(r[0]), "=r"(r[1]), "=r"(r[2]), "=r"(r[3]) : "r"(addr));
}

__device__ __forceinline__ void mma_bf16(float* d, const uint32_t* a,
                                         const uint32_t* b) {
    asm volatile(
        "mma.sync.aligned.m16n8k16.row.col.f32.bf16.bf16.f32 "
        "{%0,%1,%2,%3}, {%4,%5,%6,%7}, {%8,%9}, {%0,%1,%2,%3};"
        : "+f"(d[0]), "+f"(d[1]), "+f"(d[2]), "+f"(d[3])
        : "r"(a[0]), "r"(a[1]), "r"(a[2]), "r"(a[3]), "r"(b[0]), "r"(b[1]));
}

__device__ __forceinline__ void mma_s8(int* d, const uint32_t* a,
                                       const uint32_t* b) {
    asm volatile(
        "mma.sync.aligned.m16n8k32.row.col.s32.s8.s8.s32 "
        "{%0,%1,%2,%3}, {%4,%5,%6,%7}, {%8,%9}, {%0,%1,%2,%3};"
        : "+r"(d[0]), "+r"(d[1]), "+r"(d[2]), "+r"(d[3])
        : "r"(a[0]), "r"(a[1]), "r"(a[2]), "r"(a[3]), "r"(b[0]), "r"(b[1]));
}

__device__ __forceinline__ void cp16(uint32_t dst, const void* src) {
    asm volatile("cp.async.ca.shared.global [%0], [%1], 16;"
        :: "r"(dst), "l"((uint64_t)__cvta_generic_to_global(src)));
}
#define CP_COMMIT() asm volatile("cp.async.commit_group;")
#define CP_WAIT(n)  asm volatile("cp.async.wait_group %0;" :: "n"(n))

// ---------------------------------------------------------------------------
// Quantize rows: fp32 [rows, 2048] -> int8 h,l with per-row scale.
// w ~= s*(128*h + l), s = rowAbsMax/16256, h in [-127,127], l in [-64,64].
// One block per row; 256 threads x 8 elems.
// ---------------------------------------------------------------------------
__global__ __launch_bounds__(256) void quant_rows_kernel(
    const float* __restrict__ src, char* __restrict__ h8,
    char* __restrict__ l8, float* __restrict__ scale)
{
    const int row = blockIdx.x;
    const int tid = threadIdx.x;
    const float* r = src + (size_t)row * 2048 + tid * 8;
    float4 v0 = *(const float4*)(r);
    float4 v1 = *(const float4*)(r + 4);
    float w[8] = {v0.x, v0.y, v0.z, v0.w, v1.x, v1.y, v1.z, v1.w};

    float m = 0.f;
#pragma unroll
    for (int e = 0; e < 8; e++) m = fmaxf(m, fabsf(w[e]));
#pragma unroll
    for (int o = 16; o > 0; o >>= 1)
        m = fmaxf(m, __shfl_xor_sync(0xffffffffu, m, o));

    __shared__ float red[8];
    __shared__ float ssc;
    if ((tid & 31) == 0) red[tid >> 5] = m;
    __syncthreads();
    if (tid == 0) {
        float mm = red[0];
#pragma unroll
        for (int i = 1; i < 8; i++) mm = fmaxf(mm, red[i]);
        float s = (mm > 0.f) ? mm / 16256.f : 1.f;
        ssc = s;
        scale[row] = s;
    }
    __syncthreads();
    const float inv = 1.f / ssc;

    char h[8], l[8];
#pragma unroll
    for (int e = 0; e < 8; e++) {
        float t = w[e] * inv;               // in [-16256, 16256]
        float hq = rintf(t * (1.f / 128.f));
        float lq = rintf(t - 128.f * hq);
        h[e] = (char)(int)hq;
        l[e] = (char)(int)lq;
    }
    size_t o8 = (size_t)row * 2048 + tid * 8;
    *(uint2*)(h8 + o8) = *(uint2*)h;
    *(uint2*)(l8 + o8) = *(uint2*)l;
}

// ---------------------------------------------------------------------------
// int8 tensor-core GEMM: C = A @ W^T + bias, 3-term two-level int8.
// CTA 128x128, K-chunk 64 int8, 512 threads (16 warps, warp tile 16x64),
// 2-stage cp.async. acc_hh (x16384) and acc_x (x128, hl+lh merged).
// smem identical byte layout to bf16 version: 8 buffers x 10240B = 80KB.
// ---------------------------------------------------------------------------
#define GBM 128
#define GBN 128
#define GBK 64     // int8 per chunk (= 32 b16 units)
#define LDS 40     // b16 stride per row (80 bytes)
#define BUFB (GBM * LDS * 2)       // 10240
#define GEMM_SMEM_BYTES (BUFB * 8)

__global__ __launch_bounds__(512) void gemm_s8_kernel(
    const char* __restrict__ Ah, const char* __restrict__ Al,
    const char* __restrict__ Bh, const char* __restrict__ Bl,
    const float* __restrict__ sA, const float* __restrict__ sB,
    const float* __restrict__ bias, float* __restrict__ C,
    __nv_bfloat16* __restrict__ Chi, __nv_bfloat16* __restrict__ Clo,
    int M, int N, int K)
{
    extern __shared__ __align__(16) char dsmem[];
    const uint32_t sb = smem_u32(dsmem);

    const int tid  = threadIdx.x;
    const int lane = tid & 31;
    const int wid  = tid >> 5;      // 0..15
    const int wm   = wid & 7;       // 8 bands of 16 rows
    const int wn   = wid >> 3;      // 2 bands of 64 cols
    const size_t m0 = (size_t)blockIdx.y * GBM;
    const size_t n0 = (size_t)blockIdx.x * GBN;

    int acc_hh[8][4], acc_x[8][4];
#pragma unroll
    for (int j = 0; j < 8; j++)
#pragma unroll
        for (int e = 0; e < 4; e++) { acc_hh[j][e] = 0; acc_x[j][e] = 0; }

    // cp.async: 512 segs of 16B per matrix, one per thread
    const int ra = tid >> 2;
    const int ca = tid & 3;

    // ldmatrix addressing (b16 units; identical structure to validated bf16)
    const int a_row = wm * 16 + (lane & 15);
    const int a_col = (lane >> 4) << 3;
    const int b_row = wn * 64 + ((lane >> 4) << 3) + (lane & 7);
    const int b_col = ((lane >> 3) & 1) << 3;

    const int nChunks = K / GBK;    // 32

#define PREFETCH8(c, s) do {                                                    \
    size_t ca64 = (size_t)(c) * GBK;                                            \
    uint32_t d = (uint32_t)(ra * 80 + ca * 16);                                 \
    cp16(sb + (0 + (s)) * BUFB + d, Ah + (m0 + ra) * (size_t)K + ca64 + ca * 16); \
    cp16(sb + (2 + (s)) * BUFB + d, Al + (m0 + ra) * (size_t)K + ca64 + ca * 16); \
    cp16(sb + (4 + (s)) * BUFB + d, Bh + (n0 + ra) * (size_t)K + ca64 + ca * 16); \
    cp16(sb + (6 + (s)) * BUFB + d, Bl + (n0 + ra) * (size_t)K + ca64 + ca * 16); \
} while (0)

    PREFETCH8(0, 0);
    CP_COMMIT();

    for (int c = 0; c < nChunks; c++) {
        const int s = c & 1;
        if (c + 1 < nChunks) {
            PREFETCH8(c + 1, s ^ 1);
            CP_COMMIT();
            CP_WAIT(1);
        } else {
            CP_WAIT(0);
        }
        __syncthreads();

        const uint32_t uAh = sb + (0 + s) * BUFB;
        const uint32_t uAl = sb + (2 + s) * BUFB;
        const uint32_t uBh = sb + (4 + s) * BUFB;
        const uint32_t uBl = sb + (6 + s) * BUFB;

#pragma unroll
        for (int ks = 0; ks < 2; ks++) {       // two k32 steps per 64-chunk
            const int kk = ks * 16;            // b16 units
            uint32_t ah[4], al[4];
            uint32_t aoff = (uint32_t)((a_row * LDS + kk + a_col) * 2);
            ldsm4(ah, uAh + aoff);
            ldsm4(al, uAl + aoff);
#pragma unroll
            for (int nb = 0; nb < 4; nb++) {
                uint32_t boff = (uint32_t)(((b_row + nb * 16) * LDS + kk + b_col) * 2);
                uint32_t bh[4], bl[4];
                ldsm4(bh, uBh + boff);
                ldsm4(bl, uBl + boff);
                mma_s8(acc_hh[nb * 2 + 0], ah, bh + 0);
                mma_s8(acc_hh[nb * 2 + 1], ah, bh + 2);
                mma_s8(acc_x[nb * 2 + 0],  ah, bl + 0);
                mma_s8(acc_x[nb * 2 + 1],  ah, bl + 2);
                mma_s8(acc_x[nb * 2 + 0],  al, bh + 0);
                mma_s8(acc_x[nb * 2 + 1],  al, bh + 2);
            }
        }
        __syncthreads();
    }

    // epilogue
    const int er = lane >> 2;
    const int ec = (lane & 3) * 2;
    const size_t row0 = m0 + wm * 16 + er;
    const size_t row1 = row0 + 8;
    const float sa0 = sA[row0];
    const float sa1 = sA[row1];
#pragma unroll
    for (int nbb = 0; nbb < 8; nbb++) {
        size_t col = n0 + wn * 64 + nbb * 8 + ec;
        float sb0 = __ldg(sB + col);
        float sb1 = __ldg(sB + col + 1);
        float b0 = __ldg(bias + col);
        float b1 = __ldg(bias + col + 1);
        float v00 = sa0 * sb0 * (16384.f * (float)acc_hh[nbb][0] + 128.f * (float)acc_x[nbb][0]) + b0;
        float v01 = sa0 * sb1 * (16384.f * (float)acc_hh[nbb][1] + 128.f * (float)acc_x[nbb][1]) + b1;
        float v10 = sa1 * sb0 * (16384.f * (float)acc_hh[nbb][2] + 128.f * (float)acc_x[nbb][2]) + b0;
        float v11 = sa1 * sb1 * (16384.f * (float)acc_hh[nbb][3] + 128.f * (float)acc_x[nbb][3]) + b1;
        if (C) {
            *(float2*)(C + row0 * (size_t)N + col) = make_float2(v00, v01);
            *(float2*)(C + row1 * (size_t)N + col) = make_float2(v10, v11);
        }
        if (Chi) {
            __nv_bfloat16 h00 = __float2bfloat16(v00);
            __nv_bfloat16 h01 = __float2bfloat16(v01);
            __nv_bfloat16 h10 = __float2bfloat16(v10);
            __nv_bfloat16 h11 = __float2bfloat16(v11);
            __nv_bfloat162 hi0; hi0.x = h00; hi0.y = h01;
            __nv_bfloat162 hi1; hi1.x = h10; hi1.y = h11;
            __nv_bfloat162 lo0;
            lo0.x = __float2bfloat16(v00 - __bfloat162float(h00));
            lo0.y = __float2bfloat16(v01 - __bfloat162float(h01));
            __nv_bfloat162 lo1;
            lo1.x = __float2bfloat16(v10 - __bfloat162float(h10));
            lo1.y = __float2bfloat16(v11 - __bfloat162float(h11));
            *(__nv_bfloat162*)(Chi + row0 * (size_t)N + col) = hi0;
            *(__nv_bfloat162*)(Clo + row0 * (size_t)N + col) = lo0;
            *(__nv_bfloat162*)(Chi + row1 * (size_t)N + col) = hi1;
            *(__nv_bfloat162*)(Clo + row1 * (size_t)N + col) = lo1;
        }
    }
}

// ---------------------------------------------------------------------------
// Fused RoPE + split: reads fp32 [B,S,H,D], writes bf16 hi/lo pair.
// ---------------------------------------------------------------------------
__global__ __launch_bounds__(256) void rope_split_kernel(
    const float* __restrict__ x, const float* __restrict__ angles,
    const int* __restrict__ flag, int always,
    __nv_bfloat16* __restrict__ hi, __nv_bfloat16* __restrict__ lo)
{
    size_t i = (size_t)blockIdx.x * blockDim.x + threadIdx.x;
    const size_t total = (size_t)BB * SS * HH * DH;
    if (i >= total) return;
    const bool doRope = always || (*flag != 0);
    int half = (int)(i % DH);
    int h    = (int)((i / DH) % HH);
    int s    = (int)((i / ((size_t)DH * HH)) % SS);
    int b    = (int)(i / ((size_t)DH * HH * SS));

    size_t base = (((size_t)b * SS + s) * HH + h) * (size_t)DD;
    float x1 = x[base + half];
    float x2 = x[base + DH + half];
    float y1 = x1, y2 = x2;
    if (doRope) {
        float sn = angles[(size_t)s * DH + half];
        float cs = angles[(size_t)SS * DH + (size_t)s * DH + half];
        y1 = x1 * cs - x2 * sn;
        y2 = x1 * sn + x2 * cs;
    }
    __nv_bfloat16 h1 = __float2bfloat16(y1);
    __nv_bfloat16 h2 = __float2bfloat16(y2);
    hi[base + half]      = h1;
    hi[base + DH + half] = h2;
    lo[base + half]      = __float2bfloat16(y1 - __bfloat162float(h1));
    lo[base + DH + half] = __float2bfloat16(y2 - __bfloat162float(h2));
}

// ---------------------------------------------------------------------------
// Flash attention with 3-term split-bf16 mma.sync (VALIDATED R9).
// Epilogue writes fp32 (for re-quantization).
// ---------------------------------------------------------------------------
#define ATQ 64
#define ATK 64
#define LQK 136
#define LP  72
#define LSS 68

#define AOFF_Q   0u
#define AOFF_K   34816u
#define AOFF_V   104448u
#define AOFF_S   174080u
#define AOFF_P   191488u
#define AOFF_AL  209920u
#define AOFF_LI  210176u
#define AOFF_KM  210432u
#define ATTN_SMEM_BYTES 210944

__global__ __launch_bounds__(256, 1) void attn_mma_kernel(
    const __nv_bfloat16* __restrict__ qhi, const __nv_bfloat16* __restrict__ qlo,
    const __nv_bfloat16* __restrict__ khi, const __nv_bfloat16* __restrict__ klo,
    const __nv_bfloat16* __restrict__ vhi, const __nv_bfloat16* __restrict__ vlo,
    const int* __restrict__ amask, const int* __restrict__ causal_ptr,
    float* __restrict__ outp)
{
    extern __shared__ __align__(16) char dsmem[];
    const uint32_t sb = smem_u32(dsmem);
    float* Ss    = (float*)(dsmem + AOFF_S);
    float* sAl   = (float*)(dsmem + AOFF_AL);
    float* sLi   = (float*)(dsmem + AOFF_LI);

    const int tid  = threadIdx.x;
    const int lane = tid & 31;
    const int wid  = tid >> 5;
    const int wq   = wid & 3;
    const int wk   = wid >> 2;
    const int b  = blockIdx.x >> 4;
    const int h  = blockIdx.x & 15;
    const int q0 = blockIdx.y * ATQ;
    const int causal = *causal_ptr;

    const int ty = tid >> 4;
    const int tx = tid & 15;
    const float scale = 0.0883883476483184f;   // 1/sqrt(128)

    const int a_row = wq * 16 + (lane & 15);
    const int a_col = (lane >> 4) << 3;
    const int b_row = wk * 32 + ((lane >> 4) << 3) + (lane & 7);
    const int b_col = ((lane >> 3) & 1) << 3;
    const int vt_row = lane & 15;
    const int vt_seg = (lane >> 4) << 3;

    const size_t gq = ((size_t)b * SS + q0) * 2048 + (size_t)h * 128;
#pragma unroll
    for (int it = 0; it < 4; it++) {
        int i = tid + it * 256;
        int r = i >> 4, sg = i & 15;
        uint32_t off = (uint32_t)(r * 272 + sg * 16);
        cp16(sb + AOFF_Q + off,         qhi + gq + (size_t)r * 2048 + sg * 8);
        cp16(sb + AOFF_Q + 17408 + off, qlo + gq + (size_t)r * 2048 + sg * 8);
    }

#define PREFETCH_KV(t, s) do {                                                   \
    size_t gk = ((size_t)b * SS + (size_t)(t) * ATK) * 2048 + (size_t)h * 128;   \
    for (int it = 0; it < 4; it++) {                                             \
        int i = tid + it * 256;                                                  \
        int r = i >> 4, sg = i & 15;                                             \
        uint32_t off = (uint32_t)(r * 272 + sg * 16);                            \
        size_t go = (size_t)r * 2048 + sg * 8;                                   \
        cp16(sb + AOFF_K + (s) * 34816u + off,          khi + gk + go);          \
        cp16(sb + AOFF_K + (s) * 34816u + 17408 + off,  klo + gk + go);          \
        cp16(sb + AOFF_V + (s) * 34816u + off,          vhi + gk + go);          \
        cp16(sb + AOFF_V + (s) * 34816u + 17408 + off,  vlo + gk + go);          \
    }                                                                            \
    if (tid < 16)                                                                \
        cp16(sb + AOFF_KM + (s) * 256u + tid * 16,                               \
             amask + (size_t)b * SS + (size_t)(t) * ATK + tid * 4);              \
} while (0)

    float oacc[8][4];
#pragma unroll
    for (int j = 0; j < 8; j++)
#pragma unroll
        for (int e = 0; e < 4; e++) oacc[j][e] = 0.f;
    float mi[4], li[4];
#pragma unroll
    for (int i = 0; i < 4; i++) { mi[i] = -1e30f; li[i] = 0.f; }

    PREFETCH_KV(0, 0);
    CP_COMMIT();

    const int nTiles = SS / ATK;   // 32
    for (int t = 0; t < nTiles; t++) {
        const int s = t & 1;
        if (t + 1 < nTiles) {
            PREFETCH_KV(t + 1, s ^ 1);
            CP_COMMIT();
            CP_WAIT(1);
        } else {
            CP_WAIT(0);
        }
        __syncthreads();

        // ---- S = Q K^T (3-term) ----
        const uint32_t uQhi = sb + AOFF_Q;
        const uint32_t uQlo = sb + AOFF_Q + 17408;
        const uint32_t uKhi = sb + AOFF_K + s * 34816u;
        const uint32_t uKlo = uKhi + 17408;

        float sacc[4][4];
#pragma unroll
        for (int j = 0; j < 4; j++)
#pragma unroll
            for (int e = 0; e < 4; e++) sacc[j][e] = 0.f;

#pragma unroll
        for (int ks = 0; ks < 8; ks++) {
            const int kk = ks * 16;
            uint32_t qh[4], ql[4];
            uint32_t aoff = (uint32_t)((a_row * LQK + kk + a_col) * 2);
            ldsm4(qh, uQhi + aoff);
            ldsm4(ql, uQlo + aoff);
#pragma unroll
            for (int nb = 0; nb < 2; nb++) {
                uint32_t boff = (uint32_t)(((b_row + nb * 16) * LQK + kk + b_col) * 2);
                uint32_t bh[4], bl[4];
                ldsm4(bh, uKhi + boff);
                ldsm4(bl, uKlo + boff);
                mma_bf16(sacc[nb * 2 + 0], qh, bh + 0);
                mma_bf16(sacc[nb * 2 + 1], qh, bh + 2);
                mma_bf16(sacc[nb * 2 + 0], qh, bl + 0);
                mma_bf16(sacc[nb * 2 + 1], qh, bl + 2);
                mma_bf16(sacc[nb * 2 + 0], ql, bh + 0);
                mma_bf16(sacc[nb * 2 + 1], ql, bh + 2);
            }
        }
        {
            const int er = lane >> 2, ec = (lane & 3) * 2;
            const int srow = wq * 16 + er;
#pragma unroll
            for (int j = 0; j < 4; j++) {
                int scol = wk * 32 + (j >> 1) * 16 + (j & 1) * 8 + ec;
                Ss[srow * LSS + scol]           = sacc[j][0];
                Ss[srow * LSS + scol + 1]       = sacc[j][1];
                Ss[(srow + 8) * LSS + scol]     = sacc[j][2];
                Ss[(srow + 8) * LSS + scol + 1] = sacc[j][3];
            }
        }
        __syncthreads();

        // ---- softmax ----
        {
            const int* km = (const int*)(dsmem + AOFF_KM + s * 256u);
            float sf[4][4];
#pragma unroll
            for (int i = 0; i < 4; i++) {
                int qg = q0 + ty * 4 + i;
#pragma unroll
                for (int j = 0; j < 4; j++) {
                    int kg = t * ATK + tx * 4 + j;
                    bool ok = (km[tx * 4 + j] != 0) && (!causal || kg <= qg);
                    float sv = Ss[(ty * 4 + i) * LSS + tx * 4 + j];
                    sf[i][j] = ok ? sv * scale : -1e30f;
                }
            }
#pragma unroll
            for (int i = 0; i < 4; i++) {
                float tmax = fmaxf(fmaxf(sf[i][0], sf[i][1]), fmaxf(sf[i][2], sf[i][3]));
#pragma unroll
                for (int o = 8; o > 0; o >>= 1)
                    tmax = fmaxf(tmax, __shfl_xor_sync(0xffffffffu, tmax, o));
                float nm = fmaxf(mi[i], tmax);

                float p[4], rs = 0.f;
#pragma unroll
                for (int j = 0; j < 4; j++) {
                    p[j] = (sf[i][j] <= -1e29f) ? 0.f : __expf(sf[i][j] - nm);
                    rs += p[j];
                }
#pragma unroll
                for (int o = 8; o > 0; o >>= 1)
                    rs += __shfl_xor_sync(0xffffffffu, rs, o);

                float alpha = __expf(mi[i] - nm);
                li[i] = li[i] * alpha + rs;
                mi[i] = nm;
                sAl[ty * 4 + i] = alpha;

                __nv_bfloat16 ph[4], pl[4];
#pragma unroll
                for (int j = 0; j < 4; j++) {
                    ph[j] = __float2bfloat16(p[j]);
                    pl[j] = __float2bfloat16(p[j] - __bfloat162float(ph[j]));
                }
                uint32_t poff = (uint32_t)(((ty * 4 + i) * LP + tx * 4) * 2);
                *(uint2*)(dsmem + AOFF_P + poff)        = *(uint2*)ph;
                *(uint2*)(dsmem + AOFF_P + 9216 + poff) = *(uint2*)pl;
            }
        }
        __syncthreads();

        // ---- O = O*alpha + P V (3-term) ----
        {
            const int er = lane >> 2;
            float a0 = sAl[wq * 16 + er];
            float a1 = sAl[wq * 16 + er + 8];
#pragma unroll
            for (int j = 0; j < 8; j++) {
                oacc[j][0] *= a0; oacc[j][1] *= a0;
                oacc[j][2] *= a1; oacc[j][3] *= a1;
            }
            const uint32_t uPhi = sb + AOFF_P;
            const uint32_t uPlo = sb + AOFF_P + 9216;
            const uint32_t uVhi = sb + AOFF_V + s * 34816u;
            const uint32_t uVlo = uVhi + 17408;
#pragma unroll
            for (int ks = 0; ks < 4; ks++) {
                const int kk = ks * 16;
                uint32_t ph[4], pl[4];
                uint32_t poff = (uint32_t)((a_row * LP + kk + a_col) * 2);
                ldsm4(ph, uPhi + poff);
                ldsm4(pl, uPlo + poff);
#pragma unroll
                for (int nb = 0; nb < 4; nb++) {
                    int d0 = wk * 64 + nb * 16;
                    uint32_t voff = (uint32_t)(((kk + vt_row) * LQK + d0 + vt_seg) * 2);
                    uint32_t vh[4], vl[4];
                    ldsm4t(vh, uVhi + voff);
                    ldsm4t(vl, uVlo + voff);
                    mma_bf16(oacc[nb * 2 + 0], ph, vh + 0);
                    mma_bf16(oacc[nb * 2 + 1], ph, vh + 2);
                    mma_bf16(oacc[nb * 2 + 0], ph, vl + 0);
                    mma_bf16(oacc[nb * 2 + 1], ph, vl + 2);
                    mma_bf16(oacc[nb * 2 + 0], pl, vh + 0);
                    mma_bf16(oacc[nb * 2 + 1], pl, vh + 2);
                }
            }
        }
        __syncthreads();
    }

    sLi[ty * 4 + 0] = (li[0] > 0.f) ? 1.f / li[0] : 0.f;
    sLi[ty * 4 + 1] = (li[1] > 0.f) ? 1.f / li[1] : 0.f;
    sLi[ty * 4 + 2] = (li[2] > 0.f) ? 1.f / li[2] : 0.f;
    sLi[ty * 4 + 3] = (li[3] > 0.f) ? 1.f / li[3] : 0.f;
    __syncthreads();

    {
        const int er = lane >> 2, ec = (lane & 3) * 2;
        float inv0 = sLi[wq * 16 + er];
        float inv1 = sLi[wq * 16 + er + 8];
        size_t grow0 = ((size_t)b * SS + q0 + wq * 16 + er) * 2048;
        size_t grow1 = grow0 + (size_t)8 * 2048;
#pragma unroll
        for (int j = 0; j < 8; j++) {
            size_t colg = (size_t)h * 128 + wk * 64 + j * 8 + ec;
            *(float2*)(outp + grow0 + colg) =
                make_float2(oacc[j][0] * inv0, oacc[j][1] * inv0);
            *(float2*)(outp + grow1 + colg) =
                make_float2(oacc[j][2] * inv1, oacc[j][3] * inv1);
        }
    }
}

// ---------------------------------------------------------------------------
// Launch
// ---------------------------------------------------------------------------
extern "C" void kernel_launch(void* const* d_in, const int* in_sizes, int n_in,
                              void* d_out, int out_size)
{
    const float* x_q    = (const float*)d_in[0];
    const float* x_kv   = (const float*)d_in[1];
    const float* Wq     = (const float*)d_in[2];
    const float* bq     = (const float*)d_in[3];
    const float* Wk     = (const float*)d_in[4];
    const float* bk     = (const float*)d_in[5];
    const float* Wv     = (const float*)d_in[6];
    const float* bv     = (const float*)d_in[7];
    const float* Wo     = (const float*)d_in[8];
    const float* bo     = (const float*)d_in[9];
    const float* angles = (const float*)d_in[10];
    const int*   amask  = (const int*)d_in[11];
    const int*   causal = (const int*)d_in[12];
    const int*   k_rope = (const int*)d_in[13];
    float* out = (float*)d_out;

    float *q, *k, *attn;
    cudaGetSymbolAddress((void**)&q,    g_q);
    cudaGetSymbolAddress((void**)&k,    g_k);
    cudaGetSymbolAddress((void**)&attn, g_attn);

    char *xq_h, *xq_l, *xkv_h, *xkv_l, *at_h, *at_l;
    char *wq_h, *wq_l, *wk_h, *wk_l, *wv_h, *wv_l, *wo_h, *wo_l;
    float *sxq, *sxkv, *sat, *swq, *swk, *swv, *swo;
    cudaGetSymbolAddress((void**)&xq_h,  g_xq_h);
    cudaGetSymbolAddress((void**)&xq_l,  g_xq_l);
    cudaGetSymbolAddress((void**)&xkv_h, g_xkv_h);
    cudaGetSymbolAddress((void**)&xkv_l, g_xkv_l);
    cudaGetSymbolAddress((void**)&at_h,  g_at_h);
    cudaGetSymbolAddress((void**)&at_l,  g_at_l);
    cudaGetSymbolAddress((void**)&wq_h,  g_wq_h);
    cudaGetSymbolAddress((void**)&wq_l,  g_wq_l);
    cudaGetSymbolAddress((void**)&wk_h,  g_wk_h);
    cudaGetSymbolAddress((void**)&wk_l,  g_wk_l);
    cudaGetSymbolAddress((void**)&wv_h,  g_wv_h);
    cudaGetSymbolAddress((void**)&wv_l,  g_wv_l);
    cudaGetSymbolAddress((void**)&wo_h,  g_wo_h);
    cudaGetSymbolAddress((void**)&wo_l,  g_wo_l);
    cudaGetSymbolAddress((void**)&sxq,  g_sxq);
    cudaGetSymbolAddress((void**)&sxkv, g_sxkv);
    cudaGetSymbolAddress((void**)&sat,  g_sat);
    cudaGetSymbolAddress((void**)&swq,  g_swq);
    cudaGetSymbolAddress((void**)&swk,  g_swk);
    cudaGetSymbolAddress((void**)&swv,  g_swv);
    cudaGetSymbolAddress((void**)&swo,  g_swo);

    __nv_bfloat16 *qhi, *qlo, *khi, *klo, *vhi, *vlo;
    cudaGetSymbolAddress((void**)&qhi, g_qhi);
    cudaGetSymbolAddress((void**)&qlo, g_qlo);
    cudaGetSymbolAddress((void**)&khi, g_khi);
    cudaGetSymbolAddress((void**)&klo, g_klo);
    cudaGetSymbolAddress((void**)&vhi, g_vhi);
    cudaGetSymbolAddress((void**)&vlo, g_vlo);

    const int M = MM, N = EE, K = EE;

    cudaFuncSetAttribute(gemm_s8_kernel,
                         cudaFuncAttributeMaxDynamicSharedMemorySize, GEMM_SMEM_BYTES);
    cudaFuncSetAttribute(attn_mma_kernel,
                         cudaFuncAttributeMaxDynamicSharedMemorySize, ATTN_SMEM_BYTES);
    dim3 gGrid(N / GBN, M / GBM);   // (16, 64)

    // quantize inputs + weights
    quant_rows_kernel<<<MM, 256>>>(x_q,  xq_h,  xq_l,  sxq);
    quant_rows_kernel<<<MM, 256>>>(x_kv, xkv_h, xkv_l, sxkv);
    quant_rows_kernel<<<EE, 256>>>(Wq, wq_h, wq_l, swq);
    quant_rows_kernel<<<EE, 256>>>(Wk, wk_h, wk_l, swk);
    quant_rows_kernel<<<EE, 256>>>(Wv, wv_h, wv_l, swv);
    quant_rows_kernel<<<EE, 256>>>(Wo, wo_h, wo_l, swo);

    // projections
    gemm_s8_kernel<<<gGrid, 512, GEMM_SMEM_BYTES>>>(
        xq_h,  xq_l,  wq_h, wq_l, sxq,  swq, bq, q, nullptr, nullptr, M, N, K);
    gemm_s8_kernel<<<gGrid, 512, GEMM_SMEM_BYTES>>>(
        xkv_h, xkv_l, wk_h, wk_l, sxkv, swk, bk, k, nullptr, nullptr, M, N, K);
    gemm_s8_kernel<<<gGrid, 512, GEMM_SMEM_BYTES>>>(
        xkv_h, xkv_l, wv_h, wv_l, sxkv, swv, bv, nullptr, vhi, vlo, M, N, K);

    // fused rope + split
    size_t ropeTotal = (size_t)BB * SS * HH * DH;
    int ropeBlocks = (int)((ropeTotal + 255) / 256);
    rope_split_kernel<<<ropeBlocks, 256>>>(q, angles, k_rope, 1, qhi, qlo);
    rope_split_kernel<<<ropeBlocks, 256>>>(k, angles, k_rope, 0, khi, klo);

    // attention (bf16 3-term, fp32 out)
    dim3 aGrid(BB * HH, SS / ATQ);   // (64, 32)
    attn_mma_kernel<<<aGrid, 256, ATTN_SMEM_BYTES>>>(
        qhi, qlo, khi, klo, vhi, vlo, amask, causal, attn);

    // re-quantize attention output, final projection
    quant_rows_kernel<<<MM, 256>>>(attn, at_h, at_l, sat);
    gemm_s8_kernel<<<gGrid, 512, GEMM_SMEM_BYTES>>>(
        at_h, at_l, wo_h, wo_l, sat, swo, bo, out, nullptr, nullptr, M, N, K);
}

// round 14
// speedup vs baseline: 3.0939x; 1.1851x over previous
#include <cuda_runtime.h>
#include <cuda_bf16.h>
#include <cstdint>
#include <math.h>

// Problem constants
#define BB 4
#define SS 2048
#define EE 2048
#define HH 16
#define DD 128
#define DH 64   // DD/2

#define MM (BB * SS)              // 8192
#define NELEM ((size_t)MM * EE)   // 16,777,216
#define WELEM ((size_t)EE * EE)   // 4,194,304

// ---------------------------------------------------------------------------
// Scratch (device globals — no allocation allowed in kernel_launch)
// ---------------------------------------------------------------------------
__device__ float g_q[NELEM];
__device__ float g_k[NELEM];
__device__ float g_attn[NELEM];

__device__ char g_xq_h[NELEM],  g_xq_l[NELEM];
__device__ char g_xkv_h[NELEM], g_xkv_l[NELEM];
__device__ char g_at_h[NELEM],  g_at_l[NELEM];
__device__ char g_wq_h[WELEM], g_wq_l[WELEM];
__device__ char g_wk_h[WELEM], g_wk_l[WELEM];
__device__ char g_wv_h[WELEM], g_wv_l[WELEM];
__device__ char g_wo_h[WELEM], g_wo_l[WELEM];
__device__ float g_sxq[MM], g_sxkv[MM], g_sat[MM];
__device__ float g_swq[EE], g_swk[EE], g_swv[EE], g_swo[EE];

// attention operands
__device__ char g_q8h[NELEM], g_q8l[NELEM];
__device__ char g_k8h[NELEM], g_k8l[NELEM];
__device__ float g_sq8[(size_t)HH * MM], g_sk8[(size_t)HH * MM];  // [H][M]
__device__ __nv_bfloat16 g_vhi[NELEM], g_vlo[NELEM];

// ---------------------------------------------------------------------------
// helpers
// ---------------------------------------------------------------------------
__device__ __forceinline__ uint32_t smem_u32(const void* p) {
    uint32_t a;
    asm("{ .reg .u64 t; cvta.to.shared.u64 t, %1; cvt.u32.u64 %0, t; }"
        : "=r"(a) : "l"(p));
    return a;
}

__device__ __forceinline__ void ldsm4(uint32_t* r, uint32_t addr) {
    asm volatile("ldmatrix.sync.aligned.m8n8.x4.shared.b16 {%0,%1,%2,%3}, [%4];"
        : "=r"(r[0]), "=r"(r[1]), "=r"(r[2]), "=r"(r[3]) : "r"(addr));
}

__device__ __forceinline__ void ldsm4t(uint32_t* r, uint32_t addr) {
    asm volatile("ldmatrix.sync.aligned.m8n8.x4.trans.shared.b16 {%0,%1,%2,%3}, [%4];"
        : "=r"(r[0]), "=r"(r[1]), "=r"(r[2]), "=r"(r[3]) : "r"(addr));
}

__device__ __forceinline__ void mma_bf16(float* d, const uint32_t* a,
                                         const uint32_t* b) {
    asm volatile(
        "mma.sync.aligned.m16n8k16.row.col.f32.bf16.bf16.f32 "
        "{%0,%1,%2,%3}, {%4,%5,%6,%7}, {%8,%9}, {%0,%1,%2,%3};"
        : "+f"(d[0]), "+f"(d[1]), "+f"(d[2]), "+f"(d[3])
        : "r"(a[0]), "r"(a[1]), "r"(a[2]), "r"(a[3]), "r"(b[0]), "r"(b[1]));
}

__device__ __forceinline__ void mma_s8(int* d, const uint32_t* a,
                                       const uint32_t* b) {
    asm volatile(
        "mma.sync.aligned.m16n8k32.row.col.s32.s8.s8.s32 "
        "{%0,%1,%2,%3}, {%4,%5,%6,%7}, {%8,%9}, {%0,%1,%2,%3};"
        : "+r"(d[0]), "+r"(d[1]), "+r"(d[2]), "+r"(d[3])
        : "r"(a[0]), "r"(a[1]), "r"(a[2]), "r"(a[3]), "r"(b[0]), "r"(b[1]));
}

__device__ __forceinline__ void cp16(uint32_t dst, const void* src) {
    asm volatile("cp.async.ca.shared.global [%0], [%1], 16;"
        :: "r"(dst), "l"((uint64_t)__cvta_generic_to_global(src)));
}
#define CP_COMMIT() asm volatile("cp.async.commit_group;")
#define CP_WAIT(n)  asm volatile("cp.async.wait_group %0;" :: "n"(n))

// ---------------------------------------------------------------------------
// Quantize rows: fp32 [rows, 2048] -> int8 h,l with per-row scale.
// w ~= s*(128*h + l), s = rowAbsMax/16256.
// ---------------------------------------------------------------------------
__global__ __launch_bounds__(256) void quant_rows_kernel(
    const float* __restrict__ src, char* __restrict__ h8,
    char* __restrict__ l8, float* __restrict__ scale)
{
    const int row = blockIdx.x;
    const int tid = threadIdx.x;
    const float* r = src + (size_t)row * 2048 + tid * 8;
    float4 v0 = *(const float4*)(r);
    float4 v1 = *(const float4*)(r + 4);
    float w[8] = {v0.x, v0.y, v0.z, v0.w, v1.x, v1.y, v1.z, v1.w};

    float m = 0.f;
#pragma unroll
    for (int e = 0; e < 8; e++) m = fmaxf(m, fabsf(w[e]));
#pragma unroll
    for (int o = 16; o > 0; o >>= 1)
        m = fmaxf(m, __shfl_xor_sync(0xffffffffu, m, o));

    __shared__ float red[8];
    __shared__ float ssc;
    if ((tid & 31) == 0) red[tid >> 5] = m;
    __syncthreads();
    if (tid == 0) {
        float mm = red[0];
#pragma unroll
        for (int i = 1; i < 8; i++) mm = fmaxf(mm, red[i]);
        float s = (mm > 0.f) ? mm / 16256.f : 1.f;
        ssc = s;
        scale[row] = s;
    }
    __syncthreads();
    const float inv = 1.f / ssc;

    char h[8], l[8];
#pragma unroll
    for (int e = 0; e < 8; e++) {
        float t = w[e] * inv;
        float hq = rintf(t * (1.f / 128.f));
        float lq = rintf(t - 128.f * hq);
        h[e] = (char)(int)hq;
        l[e] = (char)(int)lq;
    }
    size_t o8 = (size_t)row * 2048 + tid * 8;
    *(uint2*)(h8 + o8) = *(uint2*)h;
    *(uint2*)(l8 + o8) = *(uint2*)l;
}

// ---------------------------------------------------------------------------
// Fused RoPE + two-level int8 quant per (b,s,h) 128-elem head-row.
// One warp per head-row; 4 warps per block. scale layout: [H][M].
// ---------------------------------------------------------------------------
__global__ __launch_bounds__(128) void rope_quant_kernel(
    const float* __restrict__ x, const float* __restrict__ angles,
    const int* __restrict__ flag, int always,
    char* __restrict__ h8, char* __restrict__ l8, float* __restrict__ scale)
{
    const int wid  = threadIdx.x >> 5;
    const int lane = threadIdx.x & 31;
    const int g = blockIdx.x * 4 + wid;          // over BB*SS*HH
    const int b    = g / (SS * HH);
    const int rem  = g % (SS * HH);
    const int spos = rem / HH;
    const int h    = rem % HH;
    const size_t base = (size_t)g * DD;
    const bool doRope = always || (*flag != 0);

    const int d0 = lane, d1 = lane + 32;
    float x1a = x[base + d0], x2a = x[base + d0 + DH];
    float x1b = x[base + d1], x2b = x[base + d1 + DH];
    float y[4];
    if (doRope) {
        float sn0 = angles[(size_t)spos * DH + d0];
        float cs0 = angles[(size_t)SS * DH + (size_t)spos * DH + d0];
        float sn1 = angles[(size_t)spos * DH + d1];
        float cs1 = angles[(size_t)SS * DH + (size_t)spos * DH + d1];
        y[0] = x1a * cs0 - x2a * sn0;
        y[1] = x1a * sn0 + x2a * cs0;
        y[2] = x1b * cs1 - x2b * sn1;
        y[3] = x1b * sn1 + x2b * cs1;
    } else {
        y[0] = x1a; y[1] = x2a; y[2] = x1b; y[3] = x2b;
    }

    float m = fmaxf(fmaxf(fabsf(y[0]), fabsf(y[1])),
                    fmaxf(fabsf(y[2]), fabsf(y[3])));
#pragma unroll
    for (int o = 16; o > 0; o >>= 1)
        m = fmaxf(m, __shfl_xor_sync(0xffffffffu, m, o));
    float s = (m > 0.f) ? m / 16256.f : 1.f;
    float inv = 1.f / s;

    char hq[4], lq[4];
#pragma unroll
    for (int e = 0; e < 4; e++) {
        float t = y[e] * inv;
        float hv = rintf(t * (1.f / 128.f));
        float lv = rintf(t - 128.f * hv);
        hq[e] = (char)(int)hv;
        lq[e] = (char)(int)lv;
    }
    h8[base + d0]      = hq[0];
    h8[base + d0 + DH] = hq[1];
    h8[base + d1]      = hq[2];
    h8[base + d1 + DH] = hq[3];
    l8[base + d0]      = lq[0];
    l8[base + d0 + DH] = lq[1];
    l8[base + d1]      = lq[2];
    l8[base + d1 + DH] = lq[3];
    if (lane == 0)
        scale[(size_t)h * MM + (size_t)b * SS + spos] = s;
}

// ---------------------------------------------------------------------------
// int8 tensor-core GEMM (VALIDATED R11): C = A @ W^T + bias, two-level 3-term.
// ---------------------------------------------------------------------------
#define GBM 128
#define GBN 128
#define GBK 64
#define LDS 40
#define BUFB (GBM * LDS * 2)       // 10240
#define GEMM_SMEM_BYTES (BUFB * 8)

__global__ __launch_bounds__(512) void gemm_s8_kernel(
    const char* __restrict__ Ah, const char* __restrict__ Al,
    const char* __restrict__ Bh, const char* __restrict__ Bl,
    const float* __restrict__ sA, const float* __restrict__ sB,
    const float* __restrict__ bias, float* __restrict__ C,
    __nv_bfloat16* __restrict__ Chi, __nv_bfloat16* __restrict__ Clo,
    int M, int N, int K)
{
    extern __shared__ __align__(16) char dsmem[];
    const uint32_t sb = smem_u32(dsmem);

    const int tid  = threadIdx.x;
    const int lane = tid & 31;
    const int wid  = tid >> 5;
    const int wm   = wid & 7;
    const int wn   = wid >> 3;
    const size_t m0 = (size_t)blockIdx.y * GBM;
    const size_t n0 = (size_t)blockIdx.x * GBN;

    int acc_hh[8][4], acc_x[8][4];
#pragma unroll
    for (int j = 0; j < 8; j++)
#pragma unroll
        for (int e = 0; e < 4; e++) { acc_hh[j][e] = 0; acc_x[j][e] = 0; }

    const int ra = tid >> 2;
    const int ca = tid & 3;

    const int a_row = wm * 16 + (lane & 15);
    const int a_col = (lane >> 4) << 3;
    const int b_row = wn * 64 + ((lane >> 4) << 3) + (lane & 7);
    const int b_col = ((lane >> 3) & 1) << 3;

    const int nChunks = K / GBK;

#define PREFETCH8(c, s) do {                                                    \
    size_t ca64 = (size_t)(c) * GBK;                                            \
    uint32_t d = (uint32_t)(ra * 80 + ca * 16);                                 \
    cp16(sb + (0 + (s)) * BUFB + d, Ah + (m0 + ra) * (size_t)K + ca64 + ca * 16); \
    cp16(sb + (2 + (s)) * BUFB + d, Al + (m0 + ra) * (size_t)K + ca64 + ca * 16); \
    cp16(sb + (4 + (s)) * BUFB + d, Bh + (n0 + ra) * (size_t)K + ca64 + ca * 16); \
    cp16(sb + (6 + (s)) * BUFB + d, Bl + (n0 + ra) * (size_t)K + ca64 + ca * 16); \
} while (0)

    PREFETCH8(0, 0);
    CP_COMMIT();

    for (int c = 0; c < nChunks; c++) {
        const int s = c & 1;
        if (c + 1 < nChunks) {
            PREFETCH8(c + 1, s ^ 1);
            CP_COMMIT();
            CP_WAIT(1);
        } else {
            CP_WAIT(0);
        }
        __syncthreads();

        const uint32_t uAh = sb + (0 + s) * BUFB;
        const uint32_t uAl = sb + (2 + s) * BUFB;
        const uint32_t uBh = sb + (4 + s) * BUFB;
        const uint32_t uBl = sb + (6 + s) * BUFB;

#pragma unroll
        for (int ks = 0; ks < 2; ks++) {
            const int kk = ks * 16;
            uint32_t ah[4], al[4];
            uint32_t aoff = (uint32_t)((a_row * LDS + kk + a_col) * 2);
            ldsm4(ah, uAh + aoff);
            ldsm4(al, uAl + aoff);
#pragma unroll
            for (int nb = 0; nb < 4; nb++) {
                uint32_t boff = (uint32_t)(((b_row + nb * 16) * LDS + kk + b_col) * 2);
                uint32_t bh[4], bl[4];
                ldsm4(bh, uBh + boff);
                ldsm4(bl, uBl + boff);
                mma_s8(acc_hh[nb * 2 + 0], ah, bh + 0);
                mma_s8(acc_hh[nb * 2 + 1], ah, bh + 2);
                mma_s8(acc_x[nb * 2 + 0],  ah, bl + 0);
                mma_s8(acc_x[nb * 2 + 1],  ah, bl + 2);
                mma_s8(acc_x[nb * 2 + 0],  al, bh + 0);
                mma_s8(acc_x[nb * 2 + 1],  al, bh + 2);
            }
        }
        __syncthreads();
    }

    const int er = lane >> 2;
    const int ec = (lane & 3) * 2;
    const size_t row0 = m0 + wm * 16 + er;
    const size_t row1 = row0 + 8;
    const float sa0 = sA[row0];
    const float sa1 = sA[row1];
#pragma unroll
    for (int nbb = 0; nbb < 8; nbb++) {
        size_t col = n0 + wn * 64 + nbb * 8 + ec;
        float sb0 = __ldg(sB + col);
        float sb1 = __ldg(sB + col + 1);
        float b0 = __ldg(bias + col);
        float b1 = __ldg(bias + col + 1);
        float v00 = sa0 * sb0 * (16384.f * (float)acc_hh[nbb][0] + 128.f * (float)acc_x[nbb][0]) + b0;
        float v01 = sa0 * sb1 * (16384.f * (float)acc_hh[nbb][1] + 128.f * (float)acc_x[nbb][1]) + b1;
        float v10 = sa1 * sb0 * (16384.f * (float)acc_hh[nbb][2] + 128.f * (float)acc_x[nbb][2]) + b0;
        float v11 = sa1 * sb1 * (16384.f * (float)acc_hh[nbb][3] + 128.f * (float)acc_x[nbb][3]) + b1;
        if (C) {
            *(float2*)(C + row0 * (size_t)N + col) = make_float2(v00, v01);
            *(float2*)(C + row1 * (size_t)N + col) = make_float2(v10, v11);
        }
        if (Chi) {
            __nv_bfloat16 h00 = __float2bfloat16(v00);
            __nv_bfloat16 h01 = __float2bfloat16(v01);
            __nv_bfloat16 h10 = __float2bfloat16(v10);
            __nv_bfloat16 h11 = __float2bfloat16(v11);
            __nv_bfloat162 hi0; hi0.x = h00; hi0.y = h01;
            __nv_bfloat162 hi1; hi1.x = h10; hi1.y = h11;
            __nv_bfloat162 lo0;
            lo0.x = __float2bfloat16(v00 - __bfloat162float(h00));
            lo0.y = __float2bfloat16(v01 - __bfloat162float(h01));
            __nv_bfloat162 lo1;
            lo1.x = __float2bfloat16(v10 - __bfloat162float(h10));
            lo1.y = __float2bfloat16(v11 - __bfloat162float(h11));
            *(__nv_bfloat162*)(Chi + row0 * (size_t)N + col) = hi0;
            *(__nv_bfloat162*)(Clo + row0 * (size_t)N + col) = lo0;
            *(__nv_bfloat162*)(Chi + row1 * (size_t)N + col) = hi1;
            *(__nv_bfloat162*)(Clo + row1 * (size_t)N + col) = lo1;
        }
    }
}

// ---------------------------------------------------------------------------
// Flash attention: int8 QK^T (two-level) + bf16 3-term PV.
// ---------------------------------------------------------------------------
#define ATQ 64
#define ATK 64
#define LQ8 72    // b16-unit stride for int8 Q/K rows (144B)
#define LQK 136   // b16-unit stride for V rows (272B)
#define LP  72
#define LSS 68

#define A8_Q   0u          // Qh 9216, Ql @+9216
#define A8_K   18432u      // +s*18432: Kh 9216, Kl @+9216
#define A8_V   55296u      // +s*34816: Vhi 17408, Vlo @+17408
#define A8_S   124928u     // 17408
#define A8_P   142336u     // Phi 9216, Plo @+9216
#define A8_SQ  160768u     // 256
#define A8_SK  161024u     // 2*256
#define A8_AL  161536u
#define A8_LI  161792u
#define A8_KM  162048u     // 2*256
#define ATTN_SMEM_BYTES 162560

__global__ __launch_bounds__(256, 1) void attn_mma_kernel(
    const char* __restrict__ q8h, const char* __restrict__ q8l,
    const char* __restrict__ k8h, const char* __restrict__ k8l,
    const float* __restrict__ sq, const float* __restrict__ sk,
    const __nv_bfloat16* __restrict__ vhi, const __nv_bfloat16* __restrict__ vlo,
    const int* __restrict__ amask, const int* __restrict__ causal_ptr,
    float* __restrict__ outp)
{
    extern __shared__ __align__(16) char dsmem[];
    const uint32_t sb = smem_u32(dsmem);
    float* Ss  = (float*)(dsmem + A8_S);
    float* sQs = (float*)(dsmem + A8_SQ);
    float* sAl = (float*)(dsmem + A8_AL);
    float* sLi = (float*)(dsmem + A8_LI);

    const int tid  = threadIdx.x;
    const int lane = tid & 31;
    const int wid  = tid >> 5;
    const int wq   = wid & 3;
    const int wk   = wid >> 2;
    const int b  = blockIdx.x >> 4;
    const int h  = blockIdx.x & 15;
    const int q0 = blockIdx.y * ATQ;
    const int causal = *causal_ptr;

    const int ty = tid >> 4;
    const int tx = tid & 15;
    const float scale = 0.0883883476483184f;   // 1/sqrt(128)

    const int a_row = wq * 16 + (lane & 15);
    const int a_col = (lane >> 4) << 3;
    const int b_row = wk * 32 + ((lane >> 4) << 3) + (lane & 7);
    const int b_col = ((lane >> 3) & 1) << 3;
    const int vt_row = lane & 15;
    const int vt_seg = (lane >> 4) << 3;

    // prologue: Q int8 h/l + sQ
    const size_t gq8 = ((size_t)b * SS + q0) * 2048 + (size_t)h * 128;
#pragma unroll
    for (int it = 0; it < 2; it++) {
        int i = tid + it * 256;
        int r = i >> 3, sg = i & 7;
        uint32_t off = (uint32_t)(r * 144 + sg * 16);
        cp16(sb + A8_Q + off,        q8h + gq8 + (size_t)r * 2048 + sg * 16);
        cp16(sb + A8_Q + 9216 + off, q8l + gq8 + (size_t)r * 2048 + sg * 16);
    }
    if (tid < 16)
        cp16(sb + A8_SQ + tid * 16, sq + (size_t)h * MM + (size_t)b * SS + q0 + tid * 4);

#define PREFETCH_KV(t, s) do {                                                   \
    size_t gk8 = ((size_t)b * SS + (size_t)(t) * ATK) * 2048 + (size_t)h * 128;  \
    for (int it = 0; it < 2; it++) {                                             \
        int i = tid + it * 256;                                                  \
        int r = i >> 3, sg = i & 7;                                              \
        uint32_t off = (uint32_t)(r * 144 + sg * 16);                            \
        cp16(sb + A8_K + (s) * 18432u + off,        k8h + gk8 + (size_t)r * 2048 + sg * 16); \
        cp16(sb + A8_K + (s) * 18432u + 9216 + off, k8l + gk8 + (size_t)r * 2048 + sg * 16); \
    }                                                                            \
    for (int it = 0; it < 4; it++) {                                             \
        int i = tid + it * 256;                                                  \
        int r = i >> 4, sg = i & 15;                                             \
        uint32_t off = (uint32_t)(r * 272 + sg * 16);                            \
        size_t go = gk8 + (size_t)r * 2048 + sg * 8;                             \
        cp16(sb + A8_V + (s) * 34816u + off,         vhi + go);                  \
        cp16(sb + A8_V + (s) * 34816u + 17408 + off, vlo + go);                  \
    }                                                                            \
    if (tid < 16)                                                                \
        cp16(sb + A8_SK + (s) * 256u + tid * 16,                                 \
             sk + (size_t)h * MM + (size_t)b * SS + (size_t)(t) * ATK + tid * 4);\
    if (tid < 16)                                                                \
        cp16(sb + A8_KM + (s) * 256u + tid * 16,                                 \
             amask + (size_t)b * SS + (size_t)(t) * ATK + tid * 4);              \
} while (0)

    float oacc[8][4];
#pragma unroll
    for (int j = 0; j < 8; j++)
#pragma unroll
        for (int e = 0; e < 4; e++) oacc[j][e] = 0.f;
    float mi[4], li[4];
#pragma unroll
    for (int i = 0; i < 4; i++) { mi[i] = -1e30f; li[i] = 0.f; }

    PREFETCH_KV(0, 0);
    CP_COMMIT();

    const int nTiles = SS / ATK;   // 32
    for (int t = 0; t < nTiles; t++) {
        const int s = t & 1;
        if (t + 1 < nTiles) {
            PREFETCH_KV(t + 1, s ^ 1);
            CP_COMMIT();
            CP_WAIT(1);
        } else {
            CP_WAIT(0);
        }
        __syncthreads();

        // ---- S = Q K^T (two-level int8, 3 terms) ----
        const uint32_t uQh = sb + A8_Q;
        const uint32_t uQl = uQh + 9216;
        const uint32_t uKh = sb + A8_K + s * 18432u;
        const uint32_t uKl = uKh + 9216;

        int shh[4][4], sxx[4][4];
#pragma unroll
        for (int j = 0; j < 4; j++)
#pragma unroll
            for (int e = 0; e < 4; e++) { shh[j][e] = 0; sxx[j][e] = 0; }

#pragma unroll
        for (int ks = 0; ks < 4; ks++) {
            const int kk = ks * 16;    // b16 units = 32 int8
            uint32_t qh[4], ql[4];
            uint32_t aoff = (uint32_t)((a_row * LQ8 + kk + a_col) * 2);
            ldsm4(qh, uQh + aoff);
            ldsm4(ql, uQl + aoff);
#pragma unroll
            for (int nb = 0; nb < 2; nb++) {
                uint32_t boff = (uint32_t)(((b_row + nb * 16) * LQ8 + kk + b_col) * 2);
                uint32_t kh[4], kl[4];
                ldsm4(kh, uKh + boff);
                ldsm4(kl, uKl + boff);
                mma_s8(shh[nb * 2 + 0], qh, kh + 0);
                mma_s8(shh[nb * 2 + 1], qh, kh + 2);
                mma_s8(sxx[nb * 2 + 0], qh, kl + 0);
                mma_s8(sxx[nb * 2 + 1], qh, kl + 2);
                mma_s8(sxx[nb * 2 + 0], ql, kh + 0);
                mma_s8(sxx[nb * 2 + 1], ql, kh + 2);
            }
        }
        {
            const float* sKs = (const float*)(dsmem + A8_SK + s * 256u);
            const int er = lane >> 2, ec = (lane & 3) * 2;
            const int srow = wq * 16 + er;
            const float sq0 = sQs[srow];
            const float sq1 = sQs[srow + 8];
#pragma unroll
            for (int j = 0; j < 4; j++) {
                int scol = wk * 32 + (j >> 1) * 16 + (j & 1) * 8 + ec;
                float f0 = sKs[scol], f1 = sKs[scol + 1];
                Ss[srow * LSS + scol] =
                    sq0 * f0 * (16384.f * (float)shh[j][0] + 128.f * (float)sxx[j][0]);
                Ss[srow * LSS + scol + 1] =
                    sq0 * f1 * (16384.f * (float)shh[j][1] + 128.f * (float)sxx[j][1]);
                Ss[(srow + 8) * LSS + scol] =
                    sq1 * f0 * (16384.f * (float)shh[j][2] + 128.f * (float)sxx[j][2]);
                Ss[(srow + 8) * LSS + scol + 1] =
                    sq1 * f1 * (16384.f * (float)shh[j][3] + 128.f * (float)sxx[j][3]);
            }
        }
        __syncthreads();

        // ---- softmax (validated) ----
        {
            const int* km = (const int*)(dsmem + A8_KM + s * 256u);
            float sf[4][4];
#pragma unroll
            for (int i = 0; i < 4; i++) {
                int qg = q0 + ty * 4 + i;
#pragma unroll
                for (int j = 0; j < 4; j++) {
                    int kg = t * ATK + tx * 4 + j;
                    bool ok = (km[tx * 4 + j] != 0) && (!causal || kg <= qg);
                    float sv = Ss[(ty * 4 + i) * LSS + tx * 4 + j];
                    sf[i][j] = ok ? sv * scale : -1e30f;
                }
            }
#pragma unroll
            for (int i = 0; i < 4; i++) {
                float tmax = fmaxf(fmaxf(sf[i][0], sf[i][1]), fmaxf(sf[i][2], sf[i][3]));
#pragma unroll
                for (int o = 8; o > 0; o >>= 1)
                    tmax = fmaxf(tmax, __shfl_xor_sync(0xffffffffu, tmax, o));
                float nm = fmaxf(mi[i], tmax);

                float p[4], rs = 0.f;
#pragma unroll
                for (int j = 0; j < 4; j++) {
                    p[j] = (sf[i][j] <= -1e29f) ? 0.f : __expf(sf[i][j] - nm);
                    rs += p[j];
                }
#pragma unroll
                for (int o = 8; o > 0; o >>= 1)
                    rs += __shfl_xor_sync(0xffffffffu, rs, o);

                float alpha = __expf(mi[i] - nm);
                li[i] = li[i] * alpha + rs;
                mi[i] = nm;
                sAl[ty * 4 + i] = alpha;

                __nv_bfloat16 ph[4], pl[4];
#pragma unroll
                for (int j = 0; j < 4; j++) {
                    ph[j] = __float2bfloat16(p[j]);
                    pl[j] = __float2bfloat16(p[j] - __bfloat162float(ph[j]));
                }
                uint32_t poff = (uint32_t)(((ty * 4 + i) * LP + tx * 4) * 2);
                *(uint2*)(dsmem + A8_P + poff)        = *(uint2*)ph;
                *(uint2*)(dsmem + A8_P + 9216 + poff) = *(uint2*)pl;
            }
        }
        __syncthreads();

        // ---- O = O*alpha + P V (bf16 3-term, validated) ----
        {
            const int er = lane >> 2;
            float a0 = sAl[wq * 16 + er];
            float a1 = sAl[wq * 16 + er + 8];
#pragma unroll
            for (int j = 0; j < 8; j++) {
                oacc[j][0] *= a0; oacc[j][1] *= a0;
                oacc[j][2] *= a1; oacc[j][3] *= a1;
            }
            const uint32_t uPhi = sb + A8_P;
            const uint32_t uPlo = sb + A8_P + 9216;
            const uint32_t uVhi = sb + A8_V + s * 34816u;
            const uint32_t uVlo = uVhi + 17408;
#pragma unroll
            for (int ks = 0; ks < 4; ks++) {
                const int kk = ks * 16;
                uint32_t ph[4], pl[4];
                uint32_t poff = (uint32_t)((a_row * LP + kk + a_col) * 2);
                ldsm4(ph, uPhi + poff);
                ldsm4(pl, uPlo + poff);
#pragma unroll
                for (int nb = 0; nb < 4; nb++) {
                    int d0 = wk * 64 + nb * 16;
                    uint32_t voff = (uint32_t)(((kk + vt_row) * LQK + d0 + vt_seg) * 2);
                    uint32_t vh[4], vl[4];
                    ldsm4t(vh, uVhi + voff);
                    ldsm4t(vl, uVlo + voff);
                    mma_bf16(oacc[nb * 2 + 0], ph, vh + 0);
                    mma_bf16(oacc[nb * 2 + 1], ph, vh + 2);
                    mma_bf16(oacc[nb * 2 + 0], ph, vl + 0);
                    mma_bf16(oacc[nb * 2 + 1], ph, vl + 2);
                    mma_bf16(oacc[nb * 2 + 0], pl, vh + 0);
                    mma_bf16(oacc[nb * 2 + 1], pl, vh + 2);
                }
            }
        }
        __syncthreads();
    }

    sLi[ty * 4 + 0] = (li[0] > 0.f) ? 1.f / li[0] : 0.f;
    sLi[ty * 4 + 1] = (li[1] > 0.f) ? 1.f / li[1] : 0.f;
    sLi[ty * 4 + 2] = (li[2] > 0.f) ? 1.f / li[2] : 0.f;
    sLi[ty * 4 + 3] = (li[3] > 0.f) ? 1.f / li[3] : 0.f;
    __syncthreads();

    {
        const int er = lane >> 2, ec = (lane & 3) * 2;
        float inv0 = sLi[wq * 16 + er];
        float inv1 = sLi[wq * 16 + er + 8];
        size_t grow0 = ((size_t)b * SS + q0 + wq * 16 + er) * 2048;
        size_t grow1 = grow0 + (size_t)8 * 2048;
#pragma unroll
        for (int j = 0; j < 8; j++) {
            size_t colg = (size_t)h * 128 + wk * 64 + j * 8 + ec;
            *(float2*)(outp + grow0 + colg) =
                make_float2(oacc[j][0] * inv0, oacc[j][1] * inv0);
            *(float2*)(outp + grow1 + colg) =
                make_float2(oacc[j][2] * inv1, oacc[j][3] * inv1);
        }
    }
}

// ---------------------------------------------------------------------------
// Launch
// ---------------------------------------------------------------------------
extern "C" void kernel_launch(void* const* d_in, const int* in_sizes, int n_in,
                              void* d_out, int out_size)
{
    const float* x_q    = (const float*)d_in[0];
    const float* x_kv   = (const float*)d_in[1];
    const float* Wq     = (const float*)d_in[2];
    const float* bq     = (const float*)d_in[3];
    const float* Wk     = (const float*)d_in[4];
    const float* bk     = (const float*)d_in[5];
    const float* Wv     = (const float*)d_in[6];
    const float* bv     = (const float*)d_in[7];
    const float* Wo     = (const float*)d_in[8];
    const float* bo     = (const float*)d_in[9];
    const float* angles = (const float*)d_in[10];
    const int*   amask  = (const int*)d_in[11];
    const int*   causal = (const int*)d_in[12];
    const int*   k_rope = (const int*)d_in[13];
    float* out = (float*)d_out;

    float *q, *k, *attn;
    cudaGetSymbolAddress((void**)&q,    g_q);
    cudaGetSymbolAddress((void**)&k,    g_k);
    cudaGetSymbolAddress((void**)&attn, g_attn);

    char *xq_h, *xq_l, *xkv_h, *xkv_l, *at_h, *at_l;
    char *wq_h, *wq_l, *wk_h, *wk_l, *wv_h, *wv_l, *wo_h, *wo_l;
    float *sxq, *sxkv, *sat, *swq, *swk, *swv, *swo;
    cudaGetSymbolAddress((void**)&xq_h,  g_xq_h);
    cudaGetSymbolAddress((void**)&xq_l,  g_xq_l);
    cudaGetSymbolAddress((void**)&xkv_h, g_xkv_h);
    cudaGetSymbolAddress((void**)&xkv_l, g_xkv_l);
    cudaGetSymbolAddress((void**)&at_h,  g_at_h);
    cudaGetSymbolAddress((void**)&at_l,  g_at_l);
    cudaGetSymbolAddress((void**)&wq_h,  g_wq_h);
    cudaGetSymbolAddress((void**)&wq_l,  g_wq_l);
    cudaGetSymbolAddress((void**)&wk_h,  g_wk_h);
    cudaGetSymbolAddress((void**)&wk_l,  g_wk_l);
    cudaGetSymbolAddress((void**)&wv_h,  g_wv_h);
    cudaGetSymbolAddress((void**)&wv_l,  g_wv_l);
    cudaGetSymbolAddress((void**)&wo_h,  g_wo_h);
    cudaGetSymbolAddress((void**)&wo_l,  g_wo_l);
    cudaGetSymbolAddress((void**)&sxq,  g_sxq);
    cudaGetSymbolAddress((void**)&sxkv, g_sxkv);
    cudaGetSymbolAddress((void**)&sat,  g_sat);
    cudaGetSymbolAddress((void**)&swq,  g_swq);
    cudaGetSymbolAddress((void**)&swk,  g_swk);
    cudaGetSymbolAddress((void**)&swv,  g_swv);
    cudaGetSymbolAddress((void**)&swo,  g_swo);

    char *q8h, *q8l, *k8h, *k8l;
    float *sq8, *sk8;
    __nv_bfloat16 *vhi, *vlo;
    cudaGetSymbolAddress((void**)&q8h, g_q8h);
    cudaGetSymbolAddress((void**)&q8l, g_q8l);
    cudaGetSymbolAddress((void**)&k8h, g_k8h);
    cudaGetSymbolAddress((void**)&k8l, g_k8l);
    cudaGetSymbolAddress((void**)&sq8, g_sq8);
    cudaGetSymbolAddress((void**)&sk8, g_sk8);
    cudaGetSymbolAddress((void**)&vhi, g_vhi);
    cudaGetSymbolAddress((void**)&vlo, g_vlo);

    const int M = MM, N = EE, K = EE;

    cudaFuncSetAttribute(gemm_s8_kernel,
                         cudaFuncAttributeMaxDynamicSharedMemorySize, GEMM_SMEM_BYTES);
    cudaFuncSetAttribute(attn_mma_kernel,
                         cudaFuncAttributeMaxDynamicSharedMemorySize, ATTN_SMEM_BYTES);
    dim3 gGrid(N / GBN, M / GBM);   // (16, 64)

    // quantize inputs + weights
    quant_rows_kernel<<<MM, 256>>>(x_q,  xq_h,  xq_l,  sxq);
    quant_rows_kernel<<<MM, 256>>>(x_kv, xkv_h, xkv_l, sxkv);
    quant_rows_kernel<<<EE, 256>>>(Wq, wq_h, wq_l, swq);
    quant_rows_kernel<<<EE, 256>>>(Wk, wk_h, wk_l, swk);
    quant_rows_kernel<<<EE, 256>>>(Wv, wv_h, wv_l, swv);
    quant_rows_kernel<<<EE, 256>>>(Wo, wo_h, wo_l, swo);

    // projections
    gemm_s8_kernel<<<gGrid, 512, GEMM_SMEM_BYTES>>>(
        xq_h,  xq_l,  wq_h, wq_l, sxq,  swq, bq, q, nullptr, nullptr, M, N, K);
    gemm_s8_kernel<<<gGrid, 512, GEMM_SMEM_BYTES>>>(
        xkv_h, xkv_l, wk_h, wk_l, sxkv, swk, bk, k, nullptr, nullptr, M, N, K);
    gemm_s8_kernel<<<gGrid, 512, GEMM_SMEM_BYTES>>>(
        xkv_h, xkv_l, wv_h, wv_l, sxkv, swv, bv, nullptr, vhi, vlo, M, N, K);

    // fused rope + int8 quant (q always; k gated on device flag)
    const int rqBlocks = BB * SS * HH / 4;   // 32768
    rope_quant_kernel<<<rqBlocks, 128>>>(q, angles, k_rope, 1, q8h, q8l, sq8);
    rope_quant_kernel<<<rqBlocks, 128>>>(k, angles, k_rope, 0, k8h, k8l, sk8);

    // attention (int8 QK^T + bf16 PV, fp32 out)
    dim3 aGrid(BB * HH, SS / ATQ);   // (64, 32)
    attn_mma_kernel<<<aGrid, 256, ATTN_SMEM_BYTES>>>(
        q8h, q8l, k8h, k8l, sq8, sk8, vhi, vlo, amask, causal, attn);

    // re-quantize attention output, final projection
    quant_rows_kernel<<<MM, 256>>>(attn, at_h, at_l, sat);
    gemm_s8_kernel<<<gGrid, 512, GEMM_SMEM_BYTES>>>(
        at_h, at_l, wo_h, wo_l, sat, swo, bo, out, nullptr, nullptr, M, N, K);
}